// round 5
// baseline (speedup 1.0000x reference)
#include <cuda_runtime.h>
#include <cstdint>

// Fused GRU cell — 3xTF32 precision-emulated mma.sync version.
//   z = sigmoid(x@Wz + h@Uz + bz)
//   r = sigmoid(x@Wr + h@Ur + br)
//   hh = tanh(x@Wh + (r*h)@Uh + bh)
//   out = z*h + (1-z)*hh
//
// Each operand split in registers: v = hi(tf32) + lo(tf32), product computed
// as lo*hi + hi*lo + hi*hi (3 MMAs) -> fp32-level accuracy on tensor cores.
//
// CTA: 64 rows (M), full 256 cols processed as 2 slabs of 128.
// Phase 1: Gr over stacked K=512 ([x|h] @ [Wr;Ur]) -> r*h into smem.
// Phase 2: Gz ([x|h]@[Wz;Uz]) and Gh ([x|rh]@[Wh;Uh]) together -> fused epilogue.
// Weights streamed via cp.async, double buffered, 8-deep K chunks.

#define HID   256
#define MT    64
#define NSLAB 128
#define XSTR  260      // x/h/rh smem row stride (floats): conflict-free A frags
#define WSTR  136      // weight smem row stride: conflict-free B frags
#define NCHUNK 64      // 512 stacked K / 8

__device__ __forceinline__ unsigned sm32(const void* p) {
    return (unsigned)__cvta_generic_to_shared(p);
}
__device__ __forceinline__ void cp16(void* s, const void* g) {
    asm volatile("cp.async.cg.shared.global [%0], [%1], 16;\n" :: "r"(sm32(s)), "l"(g));
}
__device__ __forceinline__ void cp_commit() { asm volatile("cp.async.commit_group;\n"); }
__device__ __forceinline__ void cp_wait0()  { asm volatile("cp.async.wait_group 0;\n" ::: "memory"); }

__device__ __forceinline__ unsigned tf32_rna(float v) {
    unsigned r;
    asm volatile("cvt.rna.tf32.f32 %0, %1;\n" : "=r"(r) : "f"(v));
    return r;
}
// split v into hi + lo tf32 parts (hi+lo ~ 22-bit accurate)
__device__ __forceinline__ void tf32_split(float v, unsigned& hi, unsigned& lo) {
    hi = tf32_rna(v);
    float r = v - __uint_as_float(hi);   // tf32 values are exact fp32
    lo = tf32_rna(r);
}

__device__ __forceinline__ void mma8(float c[4], const unsigned a[4], const unsigned b[2]) {
    asm volatile(
        "mma.sync.aligned.m16n8k8.row.col.f32.tf32.tf32.f32 "
        "{%0,%1,%2,%3}, {%4,%5,%6,%7}, {%8,%9}, {%0,%1,%2,%3};\n"
        : "+f"(c[0]), "+f"(c[1]), "+f"(c[2]), "+f"(c[3])
        : "r"(a[0]), "r"(a[1]), "r"(a[2]), "r"(a[3]), "r"(b[0]), "r"(b[1]));
}
// 3xTF32: c += a*b with split operands (drop lo*lo, ~2^-22 per term)
__device__ __forceinline__ void mma3(float c[4],
                                     const unsigned ahi[4], const unsigned alo[4],
                                     const unsigned bhi[2], const unsigned blo[2]) {
    mma8(c, alo, bhi);
    mma8(c, ahi, blo);
    mma8(c, ahi, bhi);
}

__device__ __forceinline__ float sigmoidf_(float v) { return 1.0f / (1.0f + __expf(-v)); }

__global__ void __launch_bounds__(256, 1)
gru_fused_tf32x3(const float* __restrict__ x,  const float* __restrict__ h,
                 const float* __restrict__ Wz, const float* __restrict__ Uz, const float* __restrict__ bz,
                 const float* __restrict__ Wr, const float* __restrict__ Ur, const float* __restrict__ br,
                 const float* __restrict__ Wh, const float* __restrict__ Uh, const float* __restrict__ bh,
                 float* __restrict__ out, float* __restrict__ out2, int rows)
{
    extern __shared__ float smem[];
    float* xs  = smem;                 // 64 x 260
    float* hs  = xs  + MT * XSTR;      // 64 x 260
    float* rhs = hs  + MT * XSTR;      // 64 x 260  (r*h)
    float* wA  = rhs + MT * XSTR;      // 2 x 8 x 136
    float* wB  = wA  + 2 * 8 * WSTR;   // 2 x 8 x 136

    const int tid  = threadIdx.x;
    const int lane = tid & 31;
    const int warp = tid >> 5;
    const int tg   = lane >> 2;   // group id (0..7)
    const int tq   = lane & 3;    // thread-in-group (0..3)
    const int m0   = (warp >> 2) * 32;  // warp M origin (0 or 32)
    const int n0w  = (warp & 3) * 32;   // warp N origin within slab (0..96)

    const int row0 = blockIdx.x * MT;

    // ---- load x / h tiles (full fp32 in smem; split happens at frag load) ----
    for (int i = tid; i < MT * 64; i += 256) {
        int r  = i >> 6;
        int c4 = (i & 63) << 2;
        int gr = row0 + r;
        float4 vx = make_float4(0.f, 0.f, 0.f, 0.f), vh = vx;
        if (gr < rows) {
            vx = *(const float4*)(x + (size_t)gr * HID + c4);
            vh = *(const float4*)(h + (size_t)gr * HID + c4);
        }
        *(float4*)(xs + r * XSTR + c4) = vx;
        *(float4*)(hs + r * XSTR + c4) = vh;
    }

    const int pr = tid >> 5;          // chunk row 0..7
    const int pc = (tid & 31) << 2;   // chunk col*4 (0..124)

    // prefetch one 8x128 weight chunk of the stacked matrix [W;U] (K=512)
    auto pfw = [&](const float* W, const float* U, int kc, int slab, float* dst) {
        int k = kc * 8 + pr;
        const float* src = (k < HID) ? (W + (size_t)k * HID) : (U + (size_t)(k - HID) * HID);
        cp16(dst + pr * WSTR + pc, src + slab * NSLAB + pc);
    };

    auto load_a = [&](unsigned ahi[2][4], unsigned alo[2][4], const float* S, int kl) {
        #pragma unroll
        for (int mt = 0; mt < 2; ++mt) {
            const float* p = S + (m0 + mt * 16 + tg) * XSTR + kl + tq;
            tf32_split(p[0],            ahi[mt][0], alo[mt][0]);
            tf32_split(p[8 * XSTR],     ahi[mt][1], alo[mt][1]);
            tf32_split(p[4],            ahi[mt][2], alo[mt][2]);
            tf32_split(p[8 * XSTR + 4], ahi[mt][3], alo[mt][3]);
        }
    };
    auto load_b = [&](unsigned bhi[4][2], unsigned blo[4][2], const float* wbuf) {
        #pragma unroll
        for (int nt = 0; nt < 4; ++nt) {
            const float* p = wbuf + tq * WSTR + n0w + nt * 8 + tg;
            tf32_split(p[0],        bhi[nt][0], blo[nt][0]);
            tf32_split(p[4 * WSTR], bhi[nt][1], blo[nt][1]);
        }
    };

    // ================= Phase 1: r = sigmoid(x@Wr + h@Ur + br); rhs = r*h =================
    for (int s = 0; s < 2; ++s) {
        float cr[2][4][4];
        #pragma unroll
        for (int i = 0; i < 2; ++i)
            #pragma unroll
            for (int j = 0; j < 4; ++j)
                #pragma unroll
                for (int k = 0; k < 4; ++k) cr[i][j][k] = 0.f;

        pfw(Wr, Ur, 0, s, wA);
        cp_commit();
        for (int kc = 0; kc < NCHUNK; ++kc) {
            cp_wait0();
            __syncthreads();
            if (kc + 1 < NCHUNK) {
                pfw(Wr, Ur, kc + 1, s, wA + ((kc + 1) & 1) * (8 * WSTR));
                cp_commit();
            }
            const float* S = (kc < 32) ? xs : hs;
            int kl = (kc & 31) * 8;
            unsigned ahi[2][4], alo[2][4], bhi[4][2], blo[4][2];
            load_a(ahi, alo, S, kl);
            load_b(bhi, blo, wA + (kc & 1) * (8 * WSTR));
            #pragma unroll
            for (int mt = 0; mt < 2; ++mt)
                #pragma unroll
                for (int nt = 0; nt < 4; ++nt)
                    mma3(cr[mt][nt], ahi[mt], alo[mt], bhi[nt], blo[nt]);
        }
        __syncthreads();
        // epilogue: rhs = sigmoid(Gr + br) * h
        #pragma unroll
        for (int nt = 0; nt < 4; ++nt) {
            int colg = s * NSLAB + n0w + nt * 8 + 2 * tq;
            float b0 = __ldg(br + colg), b1 = __ldg(br + colg + 1);
            #pragma unroll
            for (int mt = 0; mt < 2; ++mt) {
                int r0 = m0 + mt * 16 + tg;
                int r1 = r0 + 8;
                float rr;
                rr = sigmoidf_(cr[mt][nt][0] + b0); rhs[r0 * XSTR + colg    ] = rr * hs[r0 * XSTR + colg    ];
                rr = sigmoidf_(cr[mt][nt][1] + b1); rhs[r0 * XSTR + colg + 1] = rr * hs[r0 * XSTR + colg + 1];
                rr = sigmoidf_(cr[mt][nt][2] + b0); rhs[r1 * XSTR + colg    ] = rr * hs[r1 * XSTR + colg    ];
                rr = sigmoidf_(cr[mt][nt][3] + b1); rhs[r1 * XSTR + colg + 1] = rr * hs[r1 * XSTR + colg + 1];
            }
        }
        __syncthreads();
    }

    // ================= Phase 2: Gz and Gh together, fused epilogue =================
    for (int s = 0; s < 2; ++s) {
        float cz[2][4][4], ct[2][4][4];
        #pragma unroll
        for (int i = 0; i < 2; ++i)
            #pragma unroll
            for (int j = 0; j < 4; ++j)
                #pragma unroll
                for (int k = 0; k < 4; ++k) { cz[i][j][k] = 0.f; ct[i][j][k] = 0.f; }

        pfw(Wz, Uz, 0, s, wA);
        pfw(Wh, Uh, 0, s, wB);
        cp_commit();
        for (int kc = 0; kc < NCHUNK; ++kc) {
            cp_wait0();
            __syncthreads();
            if (kc + 1 < NCHUNK) {
                pfw(Wz, Uz, kc + 1, s, wA + ((kc + 1) & 1) * (8 * WSTR));
                pfw(Wh, Uh, kc + 1, s, wB + ((kc + 1) & 1) * (8 * WSTR));
                cp_commit();
            }
            int kl = (kc & 31) * 8;
            unsigned aZhi[2][4], aZlo[2][4], aHhi[2][4], aHlo[2][4];
            unsigned bZhi[4][2], bZlo[4][2], bHhi[4][2], bHlo[4][2];
            if (kc < 32) { load_a(aZhi, aZlo, xs, kl); load_a(aHhi, aHlo, xs, kl); }
            else         { load_a(aZhi, aZlo, hs, kl); load_a(aHhi, aHlo, rhs, kl); }
            load_b(bZhi, bZlo, wA + (kc & 1) * (8 * WSTR));
            load_b(bHhi, bHlo, wB + (kc & 1) * (8 * WSTR));
            #pragma unroll
            for (int mt = 0; mt < 2; ++mt)
                #pragma unroll
                for (int nt = 0; nt < 4; ++nt) {
                    mma3(cz[mt][nt], aZhi[mt], aZlo[mt], bZhi[nt], bZlo[nt]);
                    mma3(ct[mt][nt], aHhi[mt], aHlo[mt], bHhi[nt], bHlo[nt]);
                }
        }
        __syncthreads();
        // epilogue: out = z*h + (1-z)*tanh(Gh + bh)
        #pragma unroll
        for (int nt = 0; nt < 4; ++nt) {
            int colg = s * NSLAB + n0w + nt * 8 + 2 * tq;
            float bz0 = __ldg(bz + colg), bz1 = __ldg(bz + colg + 1);
            float bh0 = __ldg(bh + colg), bh1 = __ldg(bh + colg + 1);
            #pragma unroll
            for (int mt = 0; mt < 2; ++mt) {
                int r0 = m0 + mt * 16 + tg;
                int r1 = r0 + 8;
                {
                    float z0 = sigmoidf_(cz[mt][nt][0] + bz0);
                    float z1 = sigmoidf_(cz[mt][nt][1] + bz1);
                    float t0 = tanhf(ct[mt][nt][0] + bh0);
                    float t1 = tanhf(ct[mt][nt][1] + bh1);
                    float hv0 = hs[r0 * XSTR + colg];
                    float hv1 = hs[r0 * XSTR + colg + 1];
                    float o0 = z0 * hv0 + (1.f - z0) * t0;
                    float o1 = z1 * hv1 + (1.f - z1) * t1;
                    int gr = row0 + r0;
                    if (gr < rows) {
                        *(float2*)(out + (size_t)gr * HID + colg) = make_float2(o0, o1);
                        if (out2) *(float2*)(out2 + (size_t)gr * HID + colg) = make_float2(o0, o1);
                    }
                }
                {
                    float z0 = sigmoidf_(cz[mt][nt][2] + bz0);
                    float z1 = sigmoidf_(cz[mt][nt][3] + bz1);
                    float t0 = tanhf(ct[mt][nt][2] + bh0);
                    float t1 = tanhf(ct[mt][nt][3] + bh1);
                    float hv0 = hs[r1 * XSTR + colg];
                    float hv1 = hs[r1 * XSTR + colg + 1];
                    float o0 = z0 * hv0 + (1.f - z0) * t0;
                    float o1 = z1 * hv1 + (1.f - z1) * t1;
                    int gr = row0 + r1;
                    if (gr < rows) {
                        *(float2*)(out + (size_t)gr * HID + colg) = make_float2(o0, o1);
                        if (out2) *(float2*)(out2 + (size_t)gr * HID + colg) = make_float2(o0, o1);
                    }
                }
            }
        }
        __syncthreads();
    }
}

extern "C" void kernel_launch(void* const* d_in, const int* in_sizes, int n_in,
                              void* d_out, int out_size) {
    const float* x  = (const float*)d_in[0];
    const float* h  = (const float*)d_in[1];
    const float* Wz = (const float*)d_in[2];
    const float* Uz = (const float*)d_in[3];
    const float* bz = (const float*)d_in[4];
    const float* Wr = (const float*)d_in[5];
    const float* Ur = (const float*)d_in[6];
    const float* br = (const float*)d_in[7];
    const float* Wh = (const float*)d_in[8];
    const float* Uh = (const float*)d_in[9];
    const float* bh = (const float*)d_in[10];
    (void)n_in;

    int rows = in_sizes[0] / HID;
    float* out = (float*)d_out;
    float* out2 = ((long long)out_size >= 2LL * rows * HID) ? out + (size_t)rows * HID : nullptr;

    const int smem_bytes = (3 * MT * XSTR + 2 * 2 * 8 * WSTR) * (int)sizeof(float); // 217088
    cudaFuncSetAttribute(gru_fused_tf32x3, cudaFuncAttributeMaxDynamicSharedMemorySize, smem_bytes);

    int grid = (rows + MT - 1) / MT;
    gru_fused_tf32x3<<<grid, 256, smem_bytes>>>(x, h, Wz, Uz, bz, Wr, Ur, br, Wh, Uh, bh,
                                                out, out2, rows);
}

// round 6
// speedup vs baseline: 1.9842x; 1.9842x over previous
#include <cuda_runtime.h>
#include <cstdint>

// Fused GRU cell — bf16 split-precision (hi+lo, 3 MMAs) mma.sync version.
//   z = sigmoid(x@Wz + h@Uz + bz); r = sigmoid(x@Wr + h@Ur + br)
//   hh = tanh(x@Wh + (r*h)@Uh + bh); out = z*h + (1-z)*hh
//
// Weights pre-split into bf16 hi/lo packed k-pairs by a prologue kernel
// (device scratch). x/h/rh tiles stored in smem as packed bf16 hi/lo planes
// (split once at staging). Hot loop does only LDS + HMMA.16816.

#define HID   256
#define MT    64
#define NSLAB 128
#define PL    128      // uints per A-plane row (256 k-values / 2 per uint)
#define NSTR  136      // B chunk buffer row stride (uints) -> conflict-free
#define KCH   32       // k16 chunks over stacked K=512
#define WBUFU (8*NSTR) // uints per B chunk buffer

// [gate(0=z,1=r,2=h)][plane(0=hi,1=lo)][kc][kpair][n]
__device__ unsigned wscratch[3][2][KCH][8][HID];

__device__ __forceinline__ unsigned sm32(const void* p) {
    return (unsigned)__cvta_generic_to_shared(p);
}
__device__ __forceinline__ void cp16(void* s, const void* g) {
    asm volatile("cp.async.cg.shared.global [%0], [%1], 16;\n" :: "r"(sm32(s)), "l"(g));
}
__device__ __forceinline__ void cp_commit() { asm volatile("cp.async.commit_group;\n"); }
__device__ __forceinline__ void cp_wait0()  { asm volatile("cp.async.wait_group 0;\n" ::: "memory"); }

// split (x0,x1) into packed bf16 hi and lo words (lo = residual)
__device__ __forceinline__ void bsplit(float x0, float x1, unsigned& hi, unsigned& lo) {
    asm("cvt.rn.bf16x2.f32 %0, %1, %2;" : "=r"(hi) : "f"(x1), "f"(x0));
    float h0 = __uint_as_float(hi << 16);
    float h1 = __uint_as_float(hi & 0xffff0000u);
    asm("cvt.rn.bf16x2.f32 %0, %1, %2;" : "=r"(lo) : "f"(x1 - h1), "f"(x0 - h0));
}
// reconstruct (x0,x1) from packed hi/lo
__device__ __forceinline__ float2 brecon(unsigned hi, unsigned lo) {
    float2 v;
    v.x = __uint_as_float(hi << 16) + __uint_as_float(lo << 16);
    v.y = __uint_as_float(hi & 0xffff0000u) + __uint_as_float(lo & 0xffff0000u);
    return v;
}

__device__ __forceinline__ void mma16(float c[4], const unsigned a[4], const unsigned b[2]) {
    asm volatile(
        "mma.sync.aligned.m16n8k16.row.col.f32.bf16.bf16.f32 "
        "{%0,%1,%2,%3}, {%4,%5,%6,%7}, {%8,%9}, {%0,%1,%2,%3};\n"
        : "+f"(c[0]), "+f"(c[1]), "+f"(c[2]), "+f"(c[3])
        : "r"(a[0]), "r"(a[1]), "r"(a[2]), "r"(a[3]), "r"(b[0]), "r"(b[1]));
}
__device__ __forceinline__ void mma3(float c[4],
                                     const unsigned ahi[4], const unsigned alo[4],
                                     const unsigned bhi[2], const unsigned blo[2]) {
    mma16(c, alo, bhi);
    mma16(c, ahi, blo);
    mma16(c, ahi, bhi);
}

__device__ __forceinline__ float sigmoidf_(float v) { return 1.0f / (1.0f + __expf(-v)); }

// ---------------- prologue: split weights into bf16 hi/lo packed scratch --------------
__global__ void __launch_bounds__(256)
gru_split_w(const float* __restrict__ Wz, const float* __restrict__ Uz,
            const float* __restrict__ Wr, const float* __restrict__ Ur,
            const float* __restrict__ Wh, const float* __restrict__ Uh)
{
    int n  = threadIdx.x;
    int g  = blockIdx.x >> 8;       // gate
    int kp = blockIdx.x & 255;      // global k-pair over stacked K=512
    int k0 = kp << 1;
    const float* W = (g == 0) ? Wz : (g == 1) ? Wr : Wh;
    const float* U = (g == 0) ? Uz : (g == 1) ? Ur : Uh;
    const float* src = (k0 < HID) ? (W + (size_t)k0 * HID) : (U + (size_t)(k0 - HID) * HID);
    float v0 = src[n], v1 = src[HID + n];
    unsigned hi, lo;
    bsplit(v0, v1, hi, lo);
    int kc  = k0 >> 4;
    int kpl = (k0 >> 1) & 7;
    wscratch[g][0][kc][kpl][n] = hi;
    wscratch[g][1][kc][kpl][n] = lo;
}

// ---------------- main fused kernel ----------------
__global__ void __launch_bounds__(256, 1)
gru_fused_bf16x3(const float* __restrict__ x,  const float* __restrict__ h,
                 const float* __restrict__ bz, const float* __restrict__ br,
                 const float* __restrict__ bh,
                 float* __restrict__ out, float* __restrict__ out2, int rows)
{
    extern __shared__ unsigned smem_u[];
    unsigned* xhi = smem_u;              // each plane: 64 x 128 uints
    unsigned* xlo = xhi + MT * PL;
    unsigned* hhi = xlo + MT * PL;
    unsigned* hlo = hhi + MT * PL;
    unsigned* rhi = hlo + MT * PL;
    unsigned* rlo = rhi + MT * PL;
    unsigned* wb  = rlo + MT * PL;       // 8 buffers x (8 x 136) uints

    const int tid  = threadIdx.x;
    const int lane = tid & 31;
    const int warp = tid >> 5;
    const int tg   = lane >> 2;   // 0..7
    const int tq   = lane & 3;    // 0..3
    const int m0   = (warp >> 2) * 32;
    const int n0w  = (warp & 3) * 32;

    const int row0 = blockIdx.x * MT;

    // ---- stage x/h: split once into packed swizzled bf16 hi/lo planes ----
    for (int i = tid; i < MT * 64; i += 256) {
        int r  = i >> 6;
        int c4 = (i & 63) << 2;
        int gr = row0 + r;
        float4 vx = make_float4(0.f, 0.f, 0.f, 0.f), vh = vx;
        if (gr < rows) {
            vx = *(const float4*)(x + (size_t)gr * HID + c4);
            vh = *(const float4*)(h + (size_t)gr * HID + c4);
        }
        int sw  = (r & 7) << 2;
        int p0  = (c4 >> 1) ^ sw;
        int p1  = ((c4 >> 1) + 1) ^ sw;
        unsigned hi, lo;
        bsplit(vx.x, vx.y, hi, lo); xhi[r * PL + p0] = hi; xlo[r * PL + p0] = lo;
        bsplit(vx.z, vx.w, hi, lo); xhi[r * PL + p1] = hi; xlo[r * PL + p1] = lo;
        bsplit(vh.x, vh.y, hi, lo); hhi[r * PL + p0] = hi; hlo[r * PL + p0] = lo;
        bsplit(vh.z, vh.w, hi, lo); hhi[r * PL + p1] = hi; hlo[r * PL + p1] = lo;
    }

    // cp.async one weight chunk (8 kpairs x 128 n of slab) into a smem buffer
    auto pfb = [&](int gate, int plane, int kc, int slab, unsigned* dst) {
        const unsigned* blob = &wscratch[gate][plane][kc][0][0];
        int kpr = tid >> 5, seg = tid & 31;
        cp16(dst + kpr * NSTR + seg * 4, blob + kpr * HID + slab * NSLAB + seg * 4);
    };

    // A fragments: bare LDS.32 from packed planes (swizzled, conflict-free)
    auto load_a = [&](unsigned ahi[2][4], unsigned alo[2][4],
                      const unsigned* Phi, const unsigned* Plo, int klp) {
        #pragma unroll
        for (int mt = 0; mt < 2; ++mt) {
            int row = m0 + mt * 16 + tg;
            int sw  = tg << 2;
            int p0  = (klp + tq) ^ sw;
            int p1  = (klp + tq + 4) ^ sw;
            const unsigned* q0 = Phi + row * PL;
            const unsigned* q1 = Phi + (row + 8) * PL;
            ahi[mt][0] = q0[p0]; ahi[mt][1] = q1[p0];
            ahi[mt][2] = q0[p1]; ahi[mt][3] = q1[p1];
            const unsigned* s0 = Plo + row * PL;
            const unsigned* s1 = Plo + (row + 8) * PL;
            alo[mt][0] = s0[p0]; alo[mt][1] = s1[p0];
            alo[mt][2] = s0[p1]; alo[mt][3] = s1[p1];
        }
    };
    auto load_b = [&](unsigned bf[4][2], const unsigned* buf) {
        #pragma unroll
        for (int nt = 0; nt < 4; ++nt) {
            int nloc = n0w + nt * 8 + tg;
            bf[nt][0] = buf[tq * NSTR + nloc];
            bf[nt][1] = buf[(tq + 4) * NSTR + nloc];
        }
    };

    // ================= Phase 1: r gate -> rhs = sigmoid(Gr+br)*h (packed planes) ======
    for (int s = 0; s < 2; ++s) {
        float cr[2][4][4];
        #pragma unroll
        for (int i = 0; i < 2; ++i)
            #pragma unroll
            for (int j = 0; j < 4; ++j)
                #pragma unroll
                for (int k = 0; k < 4; ++k) cr[i][j][k] = 0.f;

        pfb(1, 0, 0, s, wb + 0 * WBUFU);
        pfb(1, 1, 0, s, wb + 1 * WBUFU);
        cp_commit();
        for (int kc = 0; kc < KCH; ++kc) {
            cp_wait0();
            __syncthreads();
            if (kc + 1 < KCH) {
                int nb = ((kc + 1) & 1) * 4;
                pfb(1, 0, kc + 1, s, wb + nb * WBUFU);
                pfb(1, 1, kc + 1, s, wb + (nb + 1) * WBUFU);
                cp_commit();
            }
            int klp = (kc & 15) * 8;
            const unsigned* Phi = (kc < 16) ? xhi : hhi;
            const unsigned* Plo = (kc < 16) ? xlo : hlo;
            unsigned ahi[2][4], alo[2][4], bhi[4][2], blo[4][2];
            load_a(ahi, alo, Phi, Plo, klp);
            int cb = (kc & 1) * 4;
            load_b(bhi, wb + cb * WBUFU);
            load_b(blo, wb + (cb + 1) * WBUFU);
            #pragma unroll
            for (int mt = 0; mt < 2; ++mt)
                #pragma unroll
                for (int nt = 0; nt < 4; ++nt)
                    mma3(cr[mt][nt], ahi[mt], alo[mt], bhi[nt], blo[nt]);
        }
        __syncthreads();   // buffers fully consumed before next-slab prefetch

        #pragma unroll
        for (int nt = 0; nt < 4; ++nt) {
            int colg = s * NSLAB + n0w + nt * 8 + 2 * tq;
            int kp   = colg >> 1;
            float b0 = __ldg(br + colg), b1 = __ldg(br + colg + 1);
            #pragma unroll
            for (int mt = 0; mt < 2; ++mt) {
                int r0 = m0 + mt * 16 + tg;
                int r1 = r0 + 8;
                int pos = kp ^ (tg << 2);
                float2 hv0 = brecon(hhi[r0 * PL + pos], hlo[r0 * PL + pos]);
                float2 hv1 = brecon(hhi[r1 * PL + pos], hlo[r1 * PL + pos]);
                float v00 = sigmoidf_(cr[mt][nt][0] + b0) * hv0.x;
                float v01 = sigmoidf_(cr[mt][nt][1] + b1) * hv0.y;
                float v10 = sigmoidf_(cr[mt][nt][2] + b0) * hv1.x;
                float v11 = sigmoidf_(cr[mt][nt][3] + b1) * hv1.y;
                unsigned hi, lo;
                bsplit(v00, v01, hi, lo); rhi[r0 * PL + pos] = hi; rlo[r0 * PL + pos] = lo;
                bsplit(v10, v11, hi, lo); rhi[r1 * PL + pos] = hi; rlo[r1 * PL + pos] = lo;
            }
        }
        __syncthreads();
    }

    // ================= Phase 2: z and h gates together, fused epilogue =================
    for (int s = 0; s < 2; ++s) {
        float cz[2][4][4], ct[2][4][4];
        #pragma unroll
        for (int i = 0; i < 2; ++i)
            #pragma unroll
            for (int j = 0; j < 4; ++j)
                #pragma unroll
                for (int k = 0; k < 4; ++k) { cz[i][j][k] = 0.f; ct[i][j][k] = 0.f; }

        pfb(0, 0, 0, s, wb + 0 * WBUFU);
        pfb(0, 1, 0, s, wb + 1 * WBUFU);
        pfb(2, 0, 0, s, wb + 2 * WBUFU);
        pfb(2, 1, 0, s, wb + 3 * WBUFU);
        cp_commit();
        for (int kc = 0; kc < KCH; ++kc) {
            cp_wait0();
            __syncthreads();
            if (kc + 1 < KCH) {
                int nb = ((kc + 1) & 1) * 4;
                pfb(0, 0, kc + 1, s, wb + (nb + 0) * WBUFU);
                pfb(0, 1, kc + 1, s, wb + (nb + 1) * WBUFU);
                pfb(2, 0, kc + 1, s, wb + (nb + 2) * WBUFU);
                pfb(2, 1, kc + 1, s, wb + (nb + 3) * WBUFU);
                cp_commit();
            }
            int klp = (kc & 15) * 8;
            int cb  = (kc & 1) * 4;
            unsigned bZhi[4][2], bZlo[4][2], bHhi[4][2], bHlo[4][2];
            load_b(bZhi, wb + (cb + 0) * WBUFU);
            load_b(bZlo, wb + (cb + 1) * WBUFU);
            load_b(bHhi, wb + (cb + 2) * WBUFU);
            load_b(bHlo, wb + (cb + 3) * WBUFU);
            if (kc < 16) {
                unsigned ahi[2][4], alo[2][4];
                load_a(ahi, alo, xhi, xlo, klp);   // shared A for both gates (x region)
                #pragma unroll
                for (int mt = 0; mt < 2; ++mt)
                    #pragma unroll
                    for (int nt = 0; nt < 4; ++nt) {
                        mma3(cz[mt][nt], ahi[mt], alo[mt], bZhi[nt], bZlo[nt]);
                        mma3(ct[mt][nt], ahi[mt], alo[mt], bHhi[nt], bHlo[nt]);
                    }
            } else {
                unsigned aZhi[2][4], aZlo[2][4], aHhi[2][4], aHlo[2][4];
                load_a(aZhi, aZlo, hhi, hlo, klp);
                load_a(aHhi, aHlo, rhi, rlo, klp);
                #pragma unroll
                for (int mt = 0; mt < 2; ++mt)
                    #pragma unroll
                    for (int nt = 0; nt < 4; ++nt) {
                        mma3(cz[mt][nt], aZhi[mt], aZlo[mt], bZhi[nt], bZlo[nt]);
                        mma3(ct[mt][nt], aHhi[mt], aHlo[mt], bHhi[nt], bHlo[nt]);
                    }
            }
        }
        __syncthreads();

        #pragma unroll
        for (int nt = 0; nt < 4; ++nt) {
            int colg = s * NSLAB + n0w + nt * 8 + 2 * tq;
            int kp   = colg >> 1;
            float bz0 = __ldg(bz + colg), bz1 = __ldg(bz + colg + 1);
            float bh0 = __ldg(bh + colg), bh1 = __ldg(bh + colg + 1);
            #pragma unroll
            for (int mt = 0; mt < 2; ++mt) {
                int r0 = m0 + mt * 16 + tg;
                int r1 = r0 + 8;
                int pos = kp ^ (tg << 2);
                float2 hv0 = brecon(hhi[r0 * PL + pos], hlo[r0 * PL + pos]);
                float2 hv1 = brecon(hhi[r1 * PL + pos], hlo[r1 * PL + pos]);
                {
                    float z0 = sigmoidf_(cz[mt][nt][0] + bz0);
                    float z1 = sigmoidf_(cz[mt][nt][1] + bz1);
                    float t0 = tanhf(ct[mt][nt][0] + bh0);
                    float t1 = tanhf(ct[mt][nt][1] + bh1);
                    float o0 = z0 * hv0.x + (1.f - z0) * t0;
                    float o1 = z1 * hv0.y + (1.f - z1) * t1;
                    int gr = row0 + r0;
                    if (gr < rows) {
                        *(float2*)(out + (size_t)gr * HID + colg) = make_float2(o0, o1);
                        if (out2) *(float2*)(out2 + (size_t)gr * HID + colg) = make_float2(o0, o1);
                    }
                }
                {
                    float z0 = sigmoidf_(cz[mt][nt][2] + bz0);
                    float z1 = sigmoidf_(cz[mt][nt][3] + bz1);
                    float t0 = tanhf(ct[mt][nt][2] + bh0);
                    float t1 = tanhf(ct[mt][nt][3] + bh1);
                    float o0 = z0 * hv1.x + (1.f - z0) * t0;
                    float o1 = z1 * hv1.y + (1.f - z1) * t1;
                    int gr = row0 + r1;
                    if (gr < rows) {
                        *(float2*)(out + (size_t)gr * HID + colg) = make_float2(o0, o1);
                        if (out2) *(float2*)(out2 + (size_t)gr * HID + colg) = make_float2(o0, o1);
                    }
                }
            }
        }
        __syncthreads();
    }
}

extern "C" void kernel_launch(void* const* d_in, const int* in_sizes, int n_in,
                              void* d_out, int out_size) {
    const float* x  = (const float*)d_in[0];
    const float* h  = (const float*)d_in[1];
    const float* Wz = (const float*)d_in[2];
    const float* Uz = (const float*)d_in[3];
    const float* bz = (const float*)d_in[4];
    const float* Wr = (const float*)d_in[5];
    const float* Ur = (const float*)d_in[6];
    const float* br = (const float*)d_in[7];
    const float* Wh = (const float*)d_in[8];
    const float* Uh = (const float*)d_in[9];
    const float* bh = (const float*)d_in[10];
    (void)n_in;

    int rows = in_sizes[0] / HID;
    float* out  = (float*)d_out;
    float* out2 = ((long long)out_size >= 2LL * rows * HID) ? out + (size_t)rows * HID : nullptr;

    // prologue: split weights into bf16 hi/lo packed scratch (device global)
    gru_split_w<<<768, 256>>>(Wz, Uz, Wr, Ur, Wh, Uh);

    const int smem_bytes = (6 * MT * PL + 8 * WBUFU) * (int)sizeof(unsigned); // 231424
    cudaFuncSetAttribute(gru_fused_bf16x3, cudaFuncAttributeMaxDynamicSharedMemorySize, smem_bytes);

    int grid = (rows + MT - 1) / MT;
    gru_fused_bf16x3<<<grid, 256, smem_bytes>>>(x, h, bz, br, bh, out, out2, rows);
}

// round 7
// speedup vs baseline: 1.9843x; 1.0000x over previous
#include <cuda_runtime.h>
#include <cstdint>

// Fused GRU cell — bf16 split-precision (hi+lo, 3 MMAs) mma.sync version.
//   z = sigmoid(x@Wz + h@Uz + bz); r = sigmoid(x@Wr + h@Ur + br)
//   hh = tanh(x@Wh + (r*h)@Uh + bh); out = z*h + (1-z)*hh
//
// Weights pre-split into bf16 hi/lo packed k-pairs by a prologue kernel
// (device scratch). x/h/rh tiles stored in smem as packed bf16 hi/lo planes
// (split once at staging). Hot loop does only LDS + HMMA.16816.

#define HID   256
#define MT    64
#define NSLAB 128
#define PL    128      // uints per A-plane row (256 k-values / 2 per uint)
#define NSTR  136      // B chunk buffer row stride (uints) -> conflict-free
#define KCH   32       // k16 chunks over stacked K=512
#define WBUFU (8*NSTR) // uints per B chunk buffer

// [gate(0=z,1=r,2=h)][plane(0=hi,1=lo)][kc][kpair][n]
__device__ unsigned wscratch[3][2][KCH][8][HID];

__device__ __forceinline__ unsigned sm32(const void* p) {
    return (unsigned)__cvta_generic_to_shared(p);
}
__device__ __forceinline__ void cp16(void* s, const void* g) {
    asm volatile("cp.async.cg.shared.global [%0], [%1], 16;\n" :: "r"(sm32(s)), "l"(g));
}
__device__ __forceinline__ void cp_commit() { asm volatile("cp.async.commit_group;\n"); }
__device__ __forceinline__ void cp_wait0()  { asm volatile("cp.async.wait_group 0;\n" ::: "memory"); }

// split (x0,x1) into packed bf16 hi and lo words (lo = residual)
__device__ __forceinline__ void bsplit(float x0, float x1, unsigned& hi, unsigned& lo) {
    asm("cvt.rn.bf16x2.f32 %0, %1, %2;" : "=r"(hi) : "f"(x1), "f"(x0));
    float h0 = __uint_as_float(hi << 16);
    float h1 = __uint_as_float(hi & 0xffff0000u);
    asm("cvt.rn.bf16x2.f32 %0, %1, %2;" : "=r"(lo) : "f"(x1 - h1), "f"(x0 - h0));
}
// reconstruct (x0,x1) from packed hi/lo
__device__ __forceinline__ float2 brecon(unsigned hi, unsigned lo) {
    float2 v;
    v.x = __uint_as_float(hi << 16) + __uint_as_float(lo << 16);
    v.y = __uint_as_float(hi & 0xffff0000u) + __uint_as_float(lo & 0xffff0000u);
    return v;
}

__device__ __forceinline__ void mma16(float c[4], const unsigned a[4], const unsigned b[2]) {
    asm volatile(
        "mma.sync.aligned.m16n8k16.row.col.f32.bf16.bf16.f32 "
        "{%0,%1,%2,%3}, {%4,%5,%6,%7}, {%8,%9}, {%0,%1,%2,%3};\n"
        : "+f"(c[0]), "+f"(c[1]), "+f"(c[2]), "+f"(c[3])
        : "r"(a[0]), "r"(a[1]), "r"(a[2]), "r"(a[3]), "r"(b[0]), "r"(b[1]));
}
__device__ __forceinline__ void mma3(float c[4],
                                     const unsigned ahi[4], const unsigned alo[4],
                                     const unsigned bhi[2], const unsigned blo[2]) {
    mma16(c, alo, bhi);
    mma16(c, ahi, blo);
    mma16(c, ahi, bhi);
}

__device__ __forceinline__ float sigmoidf_(float v) { return 1.0f / (1.0f + __expf(-v)); }

// ---------------- prologue: split weights into bf16 hi/lo packed scratch --------------
__global__ void __launch_bounds__(256)
gru_split_w(const float* __restrict__ Wz, const float* __restrict__ Uz,
            const float* __restrict__ Wr, const float* __restrict__ Ur,
            const float* __restrict__ Wh, const float* __restrict__ Uh)
{
    int n  = threadIdx.x;
    int g  = blockIdx.x >> 8;       // gate
    int kp = blockIdx.x & 255;      // global k-pair over stacked K=512
    int k0 = kp << 1;
    const float* W = (g == 0) ? Wz : (g == 1) ? Wr : Wh;
    const float* U = (g == 0) ? Uz : (g == 1) ? Ur : Uh;
    const float* src = (k0 < HID) ? (W + (size_t)k0 * HID) : (U + (size_t)(k0 - HID) * HID);
    float v0 = src[n], v1 = src[HID + n];
    unsigned hi, lo;
    bsplit(v0, v1, hi, lo);
    int kc  = k0 >> 4;
    int kpl = (k0 >> 1) & 7;
    wscratch[g][0][kc][kpl][n] = hi;
    wscratch[g][1][kc][kpl][n] = lo;
}

// ---------------- main fused kernel ----------------
__global__ void __launch_bounds__(256, 1)
gru_fused_bf16x3(const float* __restrict__ x,  const float* __restrict__ h,
                 const float* __restrict__ bz, const float* __restrict__ br,
                 const float* __restrict__ bh,
                 float* __restrict__ out, float* __restrict__ out2, int rows)
{
    extern __shared__ unsigned smem_u[];
    unsigned* xhi = smem_u;              // each plane: 64 x 128 uints
    unsigned* xlo = xhi + MT * PL;
    unsigned* hhi = xlo + MT * PL;
    unsigned* hlo = hhi + MT * PL;
    unsigned* rhi = hlo + MT * PL;
    unsigned* rlo = rhi + MT * PL;
    unsigned* wb  = rlo + MT * PL;       // 8 buffers x (8 x 136) uints

    const int tid  = threadIdx.x;
    const int lane = tid & 31;
    const int warp = tid >> 5;
    const int tg   = lane >> 2;   // 0..7
    const int tq   = lane & 3;    // 0..3
    const int m0   = (warp >> 2) * 32;
    const int n0w  = (warp & 3) * 32;

    const int row0 = blockIdx.x * MT;

    // ---- stage x/h: split once into packed swizzled bf16 hi/lo planes ----
    for (int i = tid; i < MT * 64; i += 256) {
        int r  = i >> 6;
        int c4 = (i & 63) << 2;
        int gr = row0 + r;
        float4 vx = make_float4(0.f, 0.f, 0.f, 0.f), vh = vx;
        if (gr < rows) {
            vx = *(const float4*)(x + (size_t)gr * HID + c4);
            vh = *(const float4*)(h + (size_t)gr * HID + c4);
        }
        int sw  = (r & 7) << 2;
        int p0  = (c4 >> 1) ^ sw;
        int p1  = ((c4 >> 1) + 1) ^ sw;
        unsigned hi, lo;
        bsplit(vx.x, vx.y, hi, lo); xhi[r * PL + p0] = hi; xlo[r * PL + p0] = lo;
        bsplit(vx.z, vx.w, hi, lo); xhi[r * PL + p1] = hi; xlo[r * PL + p1] = lo;
        bsplit(vh.x, vh.y, hi, lo); hhi[r * PL + p0] = hi; hlo[r * PL + p0] = lo;
        bsplit(vh.z, vh.w, hi, lo); hhi[r * PL + p1] = hi; hlo[r * PL + p1] = lo;
    }

    // cp.async one weight chunk (8 kpairs x 128 n of slab) into a smem buffer
    auto pfb = [&](int gate, int plane, int kc, int slab, unsigned* dst) {
        const unsigned* blob = &wscratch[gate][plane][kc][0][0];
        int kpr = tid >> 5, seg = tid & 31;
        cp16(dst + kpr * NSTR + seg * 4, blob + kpr * HID + slab * NSLAB + seg * 4);
    };

    // A fragments: bare LDS.32 from packed planes (swizzled, conflict-free)
    auto load_a = [&](unsigned ahi[2][4], unsigned alo[2][4],
                      const unsigned* Phi, const unsigned* Plo, int klp) {
        #pragma unroll
        for (int mt = 0; mt < 2; ++mt) {
            int row = m0 + mt * 16 + tg;
            int sw  = tg << 2;
            int p0  = (klp + tq) ^ sw;
            int p1  = (klp + tq + 4) ^ sw;
            const unsigned* q0 = Phi + row * PL;
            const unsigned* q1 = Phi + (row + 8) * PL;
            ahi[mt][0] = q0[p0]; ahi[mt][1] = q1[p0];
            ahi[mt][2] = q0[p1]; ahi[mt][3] = q1[p1];
            const unsigned* s0 = Plo + row * PL;
            const unsigned* s1 = Plo + (row + 8) * PL;
            alo[mt][0] = s0[p0]; alo[mt][1] = s1[p0];
            alo[mt][2] = s0[p1]; alo[mt][3] = s1[p1];
        }
    };
    auto load_b = [&](unsigned bf[4][2], const unsigned* buf) {
        #pragma unroll
        for (int nt = 0; nt < 4; ++nt) {
            int nloc = n0w + nt * 8 + tg;
            bf[nt][0] = buf[tq * NSTR + nloc];
            bf[nt][1] = buf[(tq + 4) * NSTR + nloc];
        }
    };

    // ================= Phase 1: r gate -> rhs = sigmoid(Gr+br)*h (packed planes) ======
    for (int s = 0; s < 2; ++s) {
        float cr[2][4][4];
        #pragma unroll
        for (int i = 0; i < 2; ++i)
            #pragma unroll
            for (int j = 0; j < 4; ++j)
                #pragma unroll
                for (int k = 0; k < 4; ++k) cr[i][j][k] = 0.f;

        pfb(1, 0, 0, s, wb + 0 * WBUFU);
        pfb(1, 1, 0, s, wb + 1 * WBUFU);
        cp_commit();
        for (int kc = 0; kc < KCH; ++kc) {
            cp_wait0();
            __syncthreads();
            if (kc + 1 < KCH) {
                int nb = ((kc + 1) & 1) * 4;
                pfb(1, 0, kc + 1, s, wb + nb * WBUFU);
                pfb(1, 1, kc + 1, s, wb + (nb + 1) * WBUFU);
                cp_commit();
            }
            int klp = (kc & 15) * 8;
            const unsigned* Phi = (kc < 16) ? xhi : hhi;
            const unsigned* Plo = (kc < 16) ? xlo : hlo;
            unsigned ahi[2][4], alo[2][4], bhi[4][2], blo[4][2];
            load_a(ahi, alo, Phi, Plo, klp);
            int cb = (kc & 1) * 4;
            load_b(bhi, wb + cb * WBUFU);
            load_b(blo, wb + (cb + 1) * WBUFU);
            #pragma unroll
            for (int mt = 0; mt < 2; ++mt)
                #pragma unroll
                for (int nt = 0; nt < 4; ++nt)
                    mma3(cr[mt][nt], ahi[mt], alo[mt], bhi[nt], blo[nt]);
        }
        __syncthreads();   // buffers fully consumed before next-slab prefetch

        #pragma unroll
        for (int nt = 0; nt < 4; ++nt) {
            int colg = s * NSLAB + n0w + nt * 8 + 2 * tq;
            int kp   = colg >> 1;
            float b0 = __ldg(br + colg), b1 = __ldg(br + colg + 1);
            #pragma unroll
            for (int mt = 0; mt < 2; ++mt) {
                int r0 = m0 + mt * 16 + tg;
                int r1 = r0 + 8;
                int pos = kp ^ (tg << 2);
                float2 hv0 = brecon(hhi[r0 * PL + pos], hlo[r0 * PL + pos]);
                float2 hv1 = brecon(hhi[r1 * PL + pos], hlo[r1 * PL + pos]);
                float v00 = sigmoidf_(cr[mt][nt][0] + b0) * hv0.x;
                float v01 = sigmoidf_(cr[mt][nt][1] + b1) * hv0.y;
                float v10 = sigmoidf_(cr[mt][nt][2] + b0) * hv1.x;
                float v11 = sigmoidf_(cr[mt][nt][3] + b1) * hv1.y;
                unsigned hi, lo;
                bsplit(v00, v01, hi, lo); rhi[r0 * PL + pos] = hi; rlo[r0 * PL + pos] = lo;
                bsplit(v10, v11, hi, lo); rhi[r1 * PL + pos] = hi; rlo[r1 * PL + pos] = lo;
            }
        }
        __syncthreads();
    }

    // ================= Phase 2: z and h gates together, fused epilogue =================
    for (int s = 0; s < 2; ++s) {
        float cz[2][4][4], ct[2][4][4];
        #pragma unroll
        for (int i = 0; i < 2; ++i)
            #pragma unroll
            for (int j = 0; j < 4; ++j)
                #pragma unroll
                for (int k = 0; k < 4; ++k) { cz[i][j][k] = 0.f; ct[i][j][k] = 0.f; }

        pfb(0, 0, 0, s, wb + 0 * WBUFU);
        pfb(0, 1, 0, s, wb + 1 * WBUFU);
        pfb(2, 0, 0, s, wb + 2 * WBUFU);
        pfb(2, 1, 0, s, wb + 3 * WBUFU);
        cp_commit();
        for (int kc = 0; kc < KCH; ++kc) {
            cp_wait0();
            __syncthreads();
            if (kc + 1 < KCH) {
                int nb = ((kc + 1) & 1) * 4;
                pfb(0, 0, kc + 1, s, wb + (nb + 0) * WBUFU);
                pfb(0, 1, kc + 1, s, wb + (nb + 1) * WBUFU);
                pfb(2, 0, kc + 1, s, wb + (nb + 2) * WBUFU);
                pfb(2, 1, kc + 1, s, wb + (nb + 3) * WBUFU);
                cp_commit();
            }
            int klp = (kc & 15) * 8;
            int cb  = (kc & 1) * 4;
            unsigned bZhi[4][2], bZlo[4][2], bHhi[4][2], bHlo[4][2];
            load_b(bZhi, wb + (cb + 0) * WBUFU);
            load_b(bZlo, wb + (cb + 1) * WBUFU);
            load_b(bHhi, wb + (cb + 2) * WBUFU);
            load_b(bHlo, wb + (cb + 3) * WBUFU);
            if (kc < 16) {
                unsigned ahi[2][4], alo[2][4];
                load_a(ahi, alo, xhi, xlo, klp);   // shared A for both gates (x region)
                #pragma unroll
                for (int mt = 0; mt < 2; ++mt)
                    #pragma unroll
                    for (int nt = 0; nt < 4; ++nt) {
                        mma3(cz[mt][nt], ahi[mt], alo[mt], bZhi[nt], bZlo[nt]);
                        mma3(ct[mt][nt], ahi[mt], alo[mt], bHhi[nt], bHlo[nt]);
                    }
            } else {
                unsigned aZhi[2][4], aZlo[2][4], aHhi[2][4], aHlo[2][4];
                load_a(aZhi, aZlo, hhi, hlo, klp);
                load_a(aHhi, aHlo, rhi, rlo, klp);
                #pragma unroll
                for (int mt = 0; mt < 2; ++mt)
                    #pragma unroll
                    for (int nt = 0; nt < 4; ++nt) {
                        mma3(cz[mt][nt], aZhi[mt], aZlo[mt], bZhi[nt], bZlo[nt]);
                        mma3(ct[mt][nt], aHhi[mt], aHlo[mt], bHhi[nt], bHlo[nt]);
                    }
            }
        }
        __syncthreads();

        #pragma unroll
        for (int nt = 0; nt < 4; ++nt) {
            int colg = s * NSLAB + n0w + nt * 8 + 2 * tq;
            int kp   = colg >> 1;
            float bz0 = __ldg(bz + colg), bz1 = __ldg(bz + colg + 1);
            float bh0 = __ldg(bh + colg), bh1 = __ldg(bh + colg + 1);
            #pragma unroll
            for (int mt = 0; mt < 2; ++mt) {
                int r0 = m0 + mt * 16 + tg;
                int r1 = r0 + 8;
                int pos = kp ^ (tg << 2);
                float2 hv0 = brecon(hhi[r0 * PL + pos], hlo[r0 * PL + pos]);
                float2 hv1 = brecon(hhi[r1 * PL + pos], hlo[r1 * PL + pos]);
                {
                    float z0 = sigmoidf_(cz[mt][nt][0] + bz0);
                    float z1 = sigmoidf_(cz[mt][nt][1] + bz1);
                    float t0 = tanhf(ct[mt][nt][0] + bh0);
                    float t1 = tanhf(ct[mt][nt][1] + bh1);
                    float o0 = z0 * hv0.x + (1.f - z0) * t0;
                    float o1 = z1 * hv0.y + (1.f - z1) * t1;
                    int gr = row0 + r0;
                    if (gr < rows) {
                        *(float2*)(out + (size_t)gr * HID + colg) = make_float2(o0, o1);
                        if (out2) *(float2*)(out2 + (size_t)gr * HID + colg) = make_float2(o0, o1);
                    }
                }
                {
                    float z0 = sigmoidf_(cz[mt][nt][2] + bz0);
                    float z1 = sigmoidf_(cz[mt][nt][3] + bz1);
                    float t0 = tanhf(ct[mt][nt][2] + bh0);
                    float t1 = tanhf(ct[mt][nt][3] + bh1);
                    float o0 = z0 * hv1.x + (1.f - z0) * t0;
                    float o1 = z1 * hv1.y + (1.f - z1) * t1;
                    int gr = row0 + r1;
                    if (gr < rows) {
                        *(float2*)(out + (size_t)gr * HID + colg) = make_float2(o0, o1);
                        if (out2) *(float2*)(out2 + (size_t)gr * HID + colg) = make_float2(o0, o1);
                    }
                }
            }
        }
        __syncthreads();
    }
}

extern "C" void kernel_launch(void* const* d_in, const int* in_sizes, int n_in,
                              void* d_out, int out_size) {
    const float* x  = (const float*)d_in[0];
    const float* h  = (const float*)d_in[1];
    const float* Wz = (const float*)d_in[2];
    const float* Uz = (const float*)d_in[3];
    const float* bz = (const float*)d_in[4];
    const float* Wr = (const float*)d_in[5];
    const float* Ur = (const float*)d_in[6];
    const float* br = (const float*)d_in[7];
    const float* Wh = (const float*)d_in[8];
    const float* Uh = (const float*)d_in[9];
    const float* bh = (const float*)d_in[10];
    (void)n_in;

    int rows = in_sizes[0] / HID;
    float* out  = (float*)d_out;
    float* out2 = ((long long)out_size >= 2LL * rows * HID) ? out + (size_t)rows * HID : nullptr;

    // prologue: split weights into bf16 hi/lo packed scratch (device global)
    gru_split_w<<<768, 256>>>(Wz, Uz, Wr, Ur, Wh, Uh);

    const int smem_bytes = (6 * MT * PL + 8 * WBUFU) * (int)sizeof(unsigned); // 231424
    cudaFuncSetAttribute(gru_fused_bf16x3, cudaFuncAttributeMaxDynamicSharedMemorySize, smem_bytes);

    int grid = (rows + MT - 1) / MT;
    gru_fused_bf16x3<<<grid, 256, smem_bytes>>>(x, h, bz, br, bh, out, out2, rows);
}

// round 9
// speedup vs baseline: 2.5640x; 1.2921x over previous
#include <cuda_runtime.h>
#include <cstdint>

// Fused GRU cell — bf16 hi/lo split (3 MMAs) mma.sync, 2-CTA/SM version.
// 3 gate phases over stacked K=512, MT=32 rows/CTA, full N=256 per pass:
//   phase r: Gr=[x|h]@[Wr;Ur]; rh=sigmoid(Gr+br)*h overwrites h planes
//   phase h: Gh=[x|rh]@[Wh;Uh]; hh=tanh(Gh+bh) kept in regs; h restaged
//   phase z: Gz=[x|h]@[Wz;Uz]; out = z*h + (1-z)*hh
#define HID   256
#define MT    32
#define PL    128      // uints per A-plane row
#define NSTR  264      // B buffer row stride (uints), %32==8 -> conflict-free
#define KCH   32       // k16 chunks over stacked K=512
#define WBUFU (8*NSTR)

// [gate(0=z,1=r,2=h)][plane(0=hi,1=lo)][kc][kpair][n]
__device__ unsigned wscratch[3][2][KCH][8][HID];

__device__ __forceinline__ unsigned sm32(const void* p) {
    return (unsigned)__cvta_generic_to_shared(p);
}
__device__ __forceinline__ void cp16(void* s, const void* g) {
    asm volatile("cp.async.cg.shared.global [%0], [%1], 16;\n" :: "r"(sm32(s)), "l"(g));
}
__device__ __forceinline__ void cp_commit() { asm volatile("cp.async.commit_group;\n"); }
__device__ __forceinline__ void cp_wait0()  { asm volatile("cp.async.wait_group 0;\n" ::: "memory"); }

__device__ __forceinline__ void bsplit(float x0, float x1, unsigned& hi, unsigned& lo) {
    asm("cvt.rn.bf16x2.f32 %0, %1, %2;" : "=r"(hi) : "f"(x1), "f"(x0));
    float h0 = __uint_as_float(hi << 16);
    float h1 = __uint_as_float(hi & 0xffff0000u);
    asm("cvt.rn.bf16x2.f32 %0, %1, %2;" : "=r"(lo) : "f"(x1 - h1), "f"(x0 - h0));
}
__device__ __forceinline__ float2 brecon(unsigned hi, unsigned lo) {
    float2 v;
    v.x = __uint_as_float(hi << 16) + __uint_as_float(lo << 16);
    v.y = __uint_as_float(hi & 0xffff0000u) + __uint_as_float(lo & 0xffff0000u);
    return v;
}
__device__ __forceinline__ void mma16(float c[4], const unsigned a[4], const unsigned b[2]) {
    asm volatile(
        "mma.sync.aligned.m16n8k16.row.col.f32.bf16.bf16.f32 "
        "{%0,%1,%2,%3}, {%4,%5,%6,%7}, {%8,%9}, {%0,%1,%2,%3};\n"
        : "+f"(c[0]), "+f"(c[1]), "+f"(c[2]), "+f"(c[3])
        : "r"(a[0]), "r"(a[1]), "r"(a[2]), "r"(a[3]), "r"(b[0]), "r"(b[1]));
}
__device__ __forceinline__ void mma3(float c[4],
                                     const unsigned ahi[4], const unsigned alo[4],
                                     const unsigned bhi[2], const unsigned blo[2]) {
    mma16(c, alo, bhi);
    mma16(c, ahi, blo);
    mma16(c, ahi, bhi);
}
__device__ __forceinline__ float sigf(float v) { return 1.0f / (1.0f + __expf(-v)); }

// ---------------- prologue: split weights into bf16 hi/lo packed scratch --------------
__global__ void __launch_bounds__(256)
gru_split_w(const float* __restrict__ Wz, const float* __restrict__ Uz,
            const float* __restrict__ Wr, const float* __restrict__ Ur,
            const float* __restrict__ Wh, const float* __restrict__ Uh)
{
    int n  = threadIdx.x;
    int g  = blockIdx.x >> 8;
    int k0 = (blockIdx.x & 255) << 1;
    const float* W = (g == 0) ? Wz : (g == 1) ? Wr : Wh;
    const float* U = (g == 0) ? Uz : (g == 1) ? Ur : Uh;
    const float* src = (k0 < HID) ? (W + (size_t)k0 * HID) : (U + (size_t)(k0 - HID) * HID);
    unsigned hi, lo;
    bsplit(src[n], src[HID + n], hi, lo);
    int kc = k0 >> 4, kpl = (k0 >> 1) & 7;
    wscratch[g][0][kc][kpl][n] = hi;
    wscratch[g][1][kc][kpl][n] = lo;
}

// ---------------- main fused kernel ----------------
__global__ void __launch_bounds__(256, 2)
gru_fused3(const float* __restrict__ x,  const float* __restrict__ h,
           const float* __restrict__ bz, const float* __restrict__ br,
           const float* __restrict__ bh,
           float* __restrict__ out, float* __restrict__ out2, int rows)
{
    extern __shared__ unsigned smem_u[];
    unsigned* xhi = smem_u;              // 32 x 128 uints each
    unsigned* xlo = xhi + MT * PL;
    unsigned* hhi = xlo + MT * PL;       // holds h, then rh, then h again
    unsigned* hlo = hhi + MT * PL;
    unsigned* wb  = hlo + MT * PL;       // 4 buffers x (8 x 264) uints

    const int tid  = threadIdx.x;
    const int lane = tid & 31;
    const int warp = tid >> 5;
    const int tg   = lane >> 2;
    const int tq   = lane & 3;
    const int n0w  = warp * 32;          // warp N origin over full 256
    const int row0 = blockIdx.x * MT;

    // ---- stage x/h ----
    #pragma unroll
    for (int i = tid; i < MT * 64; i += 256) {
        int r  = i >> 6;
        int c4 = (i & 63) << 2;
        int gr = row0 + r;
        float4 vx = make_float4(0.f, 0.f, 0.f, 0.f), vh = vx;
        if (gr < rows) {
            vx = *(const float4*)(x + (size_t)gr * HID + c4);
            vh = *(const float4*)(h + (size_t)gr * HID + c4);
        }
        int sw = (r & 7) << 2;
        int p0 = (c4 >> 1) ^ sw;
        int p1 = ((c4 >> 1) + 1) ^ sw;
        unsigned hi, lo;
        bsplit(vx.x, vx.y, hi, lo); xhi[r * PL + p0] = hi; xlo[r * PL + p0] = lo;
        bsplit(vx.z, vx.w, hi, lo); xhi[r * PL + p1] = hi; xlo[r * PL + p1] = lo;
        bsplit(vh.x, vh.y, hi, lo); hhi[r * PL + p0] = hi; hlo[r * PL + p0] = lo;
        bsplit(vh.z, vh.w, hi, lo); hhi[r * PL + p1] = hi; hlo[r * PL + p1] = lo;
    }
    __syncthreads();

    // copy one (gate,plane,kc) 8KB weight chunk into a smem buffer
    auto pfb = [&](int gate, int plane, int kc, unsigned* dst) {
        const unsigned* blob = &wscratch[gate][plane][kc][0][0];
        #pragma unroll
        for (int j = 0; j < 2; ++j) {
            int u4  = (j * 256 + tid) * 4;
            int kpr = u4 >> 8, col = u4 & 255;
            cp16(dst + kpr * NSTR + col, blob + u4);
        }
    };
    auto load_a = [&](unsigned ahi[2][4], unsigned alo[2][4],
                      const unsigned* Phi, const unsigned* Plo, int klp) {
        #pragma unroll
        for (int mt = 0; mt < 2; ++mt) {
            int row = mt * 16 + tg;
            int sw  = tg << 2;
            int p0  = (klp + tq) ^ sw;
            int p1  = (klp + tq + 4) ^ sw;
            const unsigned* q0 = Phi + row * PL;
            const unsigned* q1 = Phi + (row + 8) * PL;
            ahi[mt][0] = q0[p0]; ahi[mt][1] = q1[p0];
            ahi[mt][2] = q0[p1]; ahi[mt][3] = q1[p1];
            const unsigned* s0 = Plo + row * PL;
            const unsigned* s1 = Plo + (row + 8) * PL;
            alo[mt][0] = s0[p0]; alo[mt][1] = s1[p0];
            alo[mt][2] = s0[p1]; alo[mt][3] = s1[p1];
        }
    };
    auto load_b = [&](unsigned bf[4][2], const unsigned* buf) {
        #pragma unroll
        for (int nt = 0; nt < 4; ++nt) {
            int nloc = n0w + nt * 8 + tg;
            bf[nt][0] = buf[tq * NSTR + nloc];
            bf[nt][1] = buf[(tq + 4) * NSTR + nloc];
        }
    };
    // one gate GEMM over stacked K=512, full N=256
    auto run_phase = [&](int gate, float (*c)[4][4]) {
        #pragma unroll
        for (int i = 0; i < 2; ++i)
            #pragma unroll
            for (int j = 0; j < 4; ++j)
                #pragma unroll
                for (int q = 0; q < 4; ++q) c[i][j][q] = 0.f;
        pfb(gate, 0, 0, wb);
        pfb(gate, 1, 0, wb + WBUFU);
        cp_commit();
        for (int kc = 0; kc < KCH; ++kc) {
            cp_wait0();
            __syncthreads();
            if (kc + 1 < KCH) {
                int nb = ((kc + 1) & 1) * 2;
                pfb(gate, 0, kc + 1, wb + nb * WBUFU);
                pfb(gate, 1, kc + 1, wb + (nb + 1) * WBUFU);
                cp_commit();
            }
            int klp = (kc & 15) * 8;
            const unsigned* Phi = (kc < 16) ? xhi : hhi;
            const unsigned* Plo = (kc < 16) ? xlo : hlo;
            unsigned ahi[2][4], alo[2][4], bhi[4][2], blo[4][2];
            load_a(ahi, alo, Phi, Plo, klp);
            int cb = (kc & 1) * 2;
            load_b(bhi, wb + cb * WBUFU);
            load_b(blo, wb + (cb + 1) * WBUFU);
            #pragma unroll
            for (int mt = 0; mt < 2; ++mt)
                #pragma unroll
                for (int nt = 0; nt < 4; ++nt)
                    mma3(c[mt][nt], ahi[mt], alo[mt], bhi[nt], blo[nt]);
        }
        __syncthreads();
    };

    float cc[2][4][4];

    // ============ phase r: rh = sigmoid(Gr+br)*h -> overwrite h planes ============
    run_phase(1, cc);
    #pragma unroll
    for (int nt = 0; nt < 4; ++nt) {
        int colg = n0w + nt * 8 + 2 * tq;
        int kp   = colg >> 1;
        float b0 = __ldg(br + colg), b1 = __ldg(br + colg + 1);
        #pragma unroll
        for (int mt = 0; mt < 2; ++mt) {
            int r0 = mt * 16 + tg, r1 = r0 + 8;
            int pos = kp ^ (tg << 2);
            float2 hv0 = brecon(hhi[r0 * PL + pos], hlo[r0 * PL + pos]);
            float2 hv1 = brecon(hhi[r1 * PL + pos], hlo[r1 * PL + pos]);
            float v00 = sigf(cc[mt][nt][0] + b0) * hv0.x;
            float v01 = sigf(cc[mt][nt][1] + b1) * hv0.y;
            float v10 = sigf(cc[mt][nt][2] + b0) * hv1.x;
            float v11 = sigf(cc[mt][nt][3] + b1) * hv1.y;
            unsigned hi, lo;
            bsplit(v00, v01, hi, lo); hhi[r0 * PL + pos] = hi; hlo[r0 * PL + pos] = lo;
            bsplit(v10, v11, hi, lo); hhi[r1 * PL + pos] = hi; hlo[r1 * PL + pos] = lo;
        }
    }
    __syncthreads();

    // ============ phase h: hh = tanh(Gh+bh) kept in regs; restage h ============
    run_phase(2, cc);
    float hhreg[2][4][4];
    #pragma unroll
    for (int nt = 0; nt < 4; ++nt) {
        int colg = n0w + nt * 8 + 2 * tq;
        float b0 = __ldg(bh + colg), b1 = __ldg(bh + colg + 1);
        #pragma unroll
        for (int mt = 0; mt < 2; ++mt) {
            hhreg[mt][nt][0] = tanhf(cc[mt][nt][0] + b0);
            hhreg[mt][nt][1] = tanhf(cc[mt][nt][1] + b1);
            hhreg[mt][nt][2] = tanhf(cc[mt][nt][2] + b0);
            hhreg[mt][nt][3] = tanhf(cc[mt][nt][3] + b1);
        }
    }
    // restage h into planes (run_phase ended with syncthreads; rh reads done)
    #pragma unroll
    for (int i = tid; i < MT * 64; i += 256) {
        int r  = i >> 6;
        int c4 = (i & 63) << 2;
        int gr = row0 + r;
        float4 vh = make_float4(0.f, 0.f, 0.f, 0.f);
        if (gr < rows) vh = *(const float4*)(h + (size_t)gr * HID + c4);
        int sw = (r & 7) << 2;
        int p0 = (c4 >> 1) ^ sw;
        int p1 = ((c4 >> 1) + 1) ^ sw;
        unsigned hi, lo;
        bsplit(vh.x, vh.y, hi, lo); hhi[r * PL + p0] = hi; hlo[r * PL + p0] = lo;
        bsplit(vh.z, vh.w, hi, lo); hhi[r * PL + p1] = hi; hlo[r * PL + p1] = lo;
    }
    __syncthreads();

    // ============ phase z + final blend ============
    run_phase(0, cc);
    #pragma unroll
    for (int nt = 0; nt < 4; ++nt) {
        int colg = n0w + nt * 8 + 2 * tq;
        int kp   = colg >> 1;
        float b0 = __ldg(bz + colg), b1 = __ldg(bz + colg + 1);
        #pragma unroll
        for (int mt = 0; mt < 2; ++mt) {
            int r0 = mt * 16 + tg, r1 = r0 + 8;
            int pos = kp ^ (tg << 2);
            float2 hv0 = brecon(hhi[r0 * PL + pos], hlo[r0 * PL + pos]);
            float2 hv1 = brecon(hhi[r1 * PL + pos], hlo[r1 * PL + pos]);
            {
                float z0 = sigf(cc[mt][nt][0] + b0);
                float z1 = sigf(cc[mt][nt][1] + b1);
                float o0 = z0 * hv0.x + (1.f - z0) * hhreg[mt][nt][0];
                float o1 = z1 * hv0.y + (1.f - z1) * hhreg[mt][nt][1];
                int gr = row0 + r0;
                if (gr < rows) {
                    *(float2*)(out + (size_t)gr * HID + colg) = make_float2(o0, o1);
                    if (out2) *(float2*)(out2 + (size_t)gr * HID + colg) = make_float2(o0, o1);
                }
            }
            {
                float z0 = sigf(cc[mt][nt][2] + b0);
                float z1 = sigf(cc[mt][nt][3] + b1);
                float o0 = z0 * hv1.x + (1.f - z0) * hhreg[mt][nt][2];
                float o1 = z1 * hv1.y + (1.f - z1) * hhreg[mt][nt][3];
                int gr = row0 + r1;
                if (gr < rows) {
                    *(float2*)(out + (size_t)gr * HID + colg) = make_float2(o0, o1);
                    if (out2) *(float2*)(out2 + (size_t)gr * HID + colg) = make_float2(o0, o1);
                }
            }
        }
    }
}

extern "C" void kernel_launch(void* const* d_in, const int* in_sizes, int n_in,
                              void* d_out, int out_size) {
    const float* x  = (const float*)d_in[0];
    const float* h  = (const float*)d_in[1];
    const float* Wz = (const float*)d_in[2];
    const float* Uz = (const float*)d_in[3];
    const float* bz = (const float*)d_in[4];
    const float* Wr = (const float*)d_in[5];
    const float* Ur = (const float*)d_in[6];
    const float* br = (const float*)d_in[7];
    const float* Wh = (const float*)d_in[8];
    const float* Uh = (const float*)d_in[9];
    const float* bh = (const float*)d_in[10];
    (void)n_in;

    int rows = in_sizes[0] / HID;
    float* out  = (float*)d_out;
    float* out2 = ((long long)out_size >= 2LL * rows * HID) ? out + (size_t)rows * HID : nullptr;

    gru_split_w<<<768, 256>>>(Wz, Uz, Wr, Ur, Wh, Uh);

    const int smem_bytes = (4 * MT * PL + 4 * WBUFU) * (int)sizeof(unsigned); // 99328
    cudaFuncSetAttribute(gru_fused3, cudaFuncAttributeMaxDynamicSharedMemorySize, smem_bytes);

    int grid = (rows + MT - 1) / MT;
    gru_fused3<<<grid, 256, smem_bytes>>>(x, h, bz, br, bh, out, out2, rows);
}

// round 10
// speedup vs baseline: 3.0952x; 1.2072x over previous
#include <cuda_runtime.h>
#include <cstdint>

// Fused GRU cell — bf16 hi/lo split (3 MMAs), mma.sync + ldmatrix, 2 CTA/SM.
// Phases over stacked K=512, MT=32 rows/CTA, full N=256 per pass:
//   phase r: Gr=[x|h]@[Wr;Ur]; rh=sigmoid(Gr+br)*h overwrites h planes
//   phase h: Gh=[x|rh]@[Wh;Uh]; hh=tanh(Gh+bh) kept in regs; h restaged
//   phase z: Gz=[x|h]@[Wz;Uz]; out = z*h + (1-z)*hh
#define HID   256
#define MT    32
#define PL    128        // uints per A-plane row (512B rows)
#define KCH   32         // k16 chunks over stacked K=512
#define BLOBU 2048       // uints per B chunk blob (8KB)

// ldmatrix-native B scratch: [gate z/r/h][plane hi/lo][kc][npair16][mat4][row8][4xuint]
__device__ unsigned wsc[3][2][KCH][BLOBU];

__device__ __forceinline__ unsigned sm32(const void* p) {
    return (unsigned)__cvta_generic_to_shared(p);
}
__device__ __forceinline__ void cp16(unsigned s, const void* g) {
    asm volatile("cp.async.cg.shared.global [%0], [%1], 16;\n" :: "r"(s), "l"(g));
}
__device__ __forceinline__ void cp_commit() { asm volatile("cp.async.commit_group;\n"); }
__device__ __forceinline__ void cp_wait0()  { asm volatile("cp.async.wait_group 0;\n" ::: "memory"); }

#define LDSM4(R0,R1,R2,R3,A) \
    asm volatile("ldmatrix.sync.aligned.m8n8.x4.shared.b16 {%0,%1,%2,%3}, [%4];" \
        : "=r"(R0), "=r"(R1), "=r"(R2), "=r"(R3) : "r"(A))

__device__ __forceinline__ void bsplit(float x0, float x1, unsigned& hi, unsigned& lo) {
    asm("cvt.rn.bf16x2.f32 %0, %1, %2;" : "=r"(hi) : "f"(x1), "f"(x0));
    float h0 = __uint_as_float(hi << 16);
    float h1 = __uint_as_float(hi & 0xffff0000u);
    asm("cvt.rn.bf16x2.f32 %0, %1, %2;" : "=r"(lo) : "f"(x1 - h1), "f"(x0 - h0));
}
__device__ __forceinline__ float2 brecon(unsigned hi, unsigned lo) {
    float2 v;
    v.x = __uint_as_float(hi << 16) + __uint_as_float(lo << 16);
    v.y = __uint_as_float(hi & 0xffff0000u) + __uint_as_float(lo & 0xffff0000u);
    return v;
}
__device__ __forceinline__ void mma16(float c[4], const unsigned a[4], const unsigned b[2]) {
    asm volatile(
        "mma.sync.aligned.m16n8k16.row.col.f32.bf16.bf16.f32 "
        "{%0,%1,%2,%3}, {%4,%5,%6,%7}, {%8,%9}, {%0,%1,%2,%3};\n"
        : "+f"(c[0]), "+f"(c[1]), "+f"(c[2]), "+f"(c[3])
        : "r"(a[0]), "r"(a[1]), "r"(a[2]), "r"(a[3]), "r"(b[0]), "r"(b[1]));
}
__device__ __forceinline__ void mma3(float c[4],
                                     const unsigned ahi[4], const unsigned alo[4],
                                     const unsigned bhi[2], const unsigned blo[2]) {
    mma16(c, alo, bhi);
    mma16(c, ahi, blo);
    mma16(c, ahi, bhi);
}
__device__ __forceinline__ float sigf(float v) { return 1.0f / (1.0f + __expf(-v)); }

// ---------------- prologue: split weights into ldmatrix-tiled bf16 hi/lo scratch ------
// blob layout per (gate,plane,kc): npair(16) x mat(4) x row(8) x 16B
//   mat = ((n>>3)&1)*2 + (kpair>>2):  r0=n0-7/k0-7, r1=n0-7/k8-15, r2=n8-15/k0-7, r3=...
__global__ void __launch_bounds__(256)
gru_split_w(const float* __restrict__ Wz, const float* __restrict__ Uz,
            const float* __restrict__ Wr, const float* __restrict__ Ur,
            const float* __restrict__ Wh, const float* __restrict__ Uh)
{
    int g  = blockIdx.x >> 5;        // gate 0=z,1=r,2=h
    int kc = blockIdx.x & 31;        // k16 chunk in stacked K
    int n  = threadIdx.x;            // 0..255
    const float* W = (g == 0) ? Wz : (g == 1) ? Wr : Wh;
    const float* U = (g == 0) ? Uz : (g == 1) ? Ur : Uh;
    float v[16];
    #pragma unroll
    for (int k = 0; k < 16; ++k) {
        int kg = kc * 16 + k;
        const float* src = (kg < HID) ? (W + (size_t)kg * HID) : (U + (size_t)(kg - HID) * HID);
        v[k] = src[n];
    }
    int npair = n >> 4, j = n & 7, msel = (n >> 3) & 1;
    unsigned base = npair * 128 + msel * 64 + j * 4;
    #pragma unroll
    for (int usel = 0; usel < 2; ++usel) {
        unsigned h4[4], l4[4];
        #pragma unroll
        for (int q = 0; q < 4; ++q) {
            int kp = usel * 4 + q;
            bsplit(v[2 * kp], v[2 * kp + 1], h4[q], l4[q]);
        }
        unsigned off = base + usel * 32;
        *(uint4*)&wsc[g][0][kc][off] = make_uint4(h4[0], h4[1], h4[2], h4[3]);
        *(uint4*)&wsc[g][1][kc][off] = make_uint4(l4[0], l4[1], l4[2], l4[3]);
    }
}

// ---------------- main fused kernel ----------------
__global__ void __launch_bounds__(256, 2)
gru_fused3(const float* __restrict__ x,  const float* __restrict__ h,
           const float* __restrict__ bz, const float* __restrict__ br,
           const float* __restrict__ bh,
           float* __restrict__ out, float* __restrict__ out2, int rows)
{
    extern __shared__ unsigned smem_u[];
    unsigned* xhi = smem_u;              // 32 x 128 uints each (16KB)
    unsigned* xlo = xhi + MT * PL;
    unsigned* hhi = xlo + MT * PL;       // holds h, then rh, then h again
    unsigned* hlo = hhi + MT * PL;
    unsigned* wb  = hlo + MT * PL;       // 4 blob buffers x 2048 uints

    const int tid  = threadIdx.x;
    const int lane = tid & 31;
    const int warp = tid >> 5;
    const int tg   = lane >> 2;
    const int tq   = lane & 3;
    const int n0w  = warp * 32;
    const int row0 = blockIdx.x * MT;

    const unsigned xhiA = sm32(xhi), xloA = sm32(xlo);
    const unsigned hhiA = sm32(hhi), hloA = sm32(hlo);
    const unsigned wbA  = sm32(wb);

    // ---- stage x/h into split packed swizzled planes ----
    #pragma unroll
    for (int i = tid; i < MT * 64; i += 256) {
        int r  = i >> 6;
        int c4 = (i & 63) << 2;
        int gr = row0 + r;
        float4 vx = make_float4(0.f, 0.f, 0.f, 0.f), vh = vx;
        if (gr < rows) {
            vx = *(const float4*)(x + (size_t)gr * HID + c4);
            vh = *(const float4*)(h + (size_t)gr * HID + c4);
        }
        int sw = (r & 7) << 2;
        int p0 = (c4 >> 1) ^ sw;
        int p1 = ((c4 >> 1) + 1) ^ sw;
        unsigned hi, lo;
        bsplit(vx.x, vx.y, hi, lo); xhi[r * PL + p0] = hi; xlo[r * PL + p0] = lo;
        bsplit(vx.z, vx.w, hi, lo); xhi[r * PL + p1] = hi; xlo[r * PL + p1] = lo;
        bsplit(vh.x, vh.y, hi, lo); hhi[r * PL + p0] = hi; hlo[r * PL + p0] = lo;
        bsplit(vh.z, vh.w, hi, lo); hhi[r * PL + p1] = hi; hlo[r * PL + p1] = lo;
    }
    __syncthreads();

    // copy one 8KB (gate,plane,kc) blob into buffer slot
    auto pfb = [&](int gate, int plane, int kc, int buf) {
        const unsigned* src = wsc[gate][plane][kc];
        unsigned dst = wbA + buf * 8192;
        cp16(dst + tid * 16, src + tid * 4);
        cp16(dst + 4096 + tid * 16, src + 1024 + tid * 4);
    };

    // ldmatrix A-frag lane geometry (constant per thread)
    const int aRowOff = (lane & 7) + ((lane >> 3) & 1) * 8;
    const int aUsel   = (lane >> 4) & 1;
    // ldmatrix B-frag lane offset within a 512B npair block
    const unsigned bOff = (unsigned)((lane >> 3) * 128 + (lane & 7) * 16);
    const unsigned bP0  = (unsigned)(warp * 2) * 512;

    auto load_a = [&](unsigned ahi[2][4], unsigned alo[2][4],
                      unsigned PhiA, unsigned PloA, int uBase) {
        #pragma unroll
        for (int mt = 0; mt < 2; ++mt) {
            int rowA = mt * 16 + aRowOff;
            unsigned swu = (unsigned)(((uBase + aUsel) ^ (rowA & 7)) << 4);
            unsigned byteOff = (unsigned)rowA * 512u + swu;
            LDSM4(ahi[mt][0], ahi[mt][1], ahi[mt][2], ahi[mt][3], PhiA + byteOff);
            LDSM4(alo[mt][0], alo[mt][1], alo[mt][2], alo[mt][3], PloA + byteOff);
        }
    };
    auto load_b = [&](unsigned bf[4][2], unsigned blobA) {
        LDSM4(bf[0][0], bf[0][1], bf[1][0], bf[1][1], blobA + bP0 + bOff);
        LDSM4(bf[2][0], bf[2][1], bf[3][0], bf[3][1], blobA + bP0 + 512 + bOff);
    };

    // one gate GEMM over stacked K=512, full N=256
    auto run_phase = [&](int gate, float (*c)[4][4]) {
        #pragma unroll
        for (int i = 0; i < 2; ++i)
            #pragma unroll
            for (int j = 0; j < 4; ++j)
                #pragma unroll
                for (int q = 0; q < 4; ++q) c[i][j][q] = 0.f;
        pfb(gate, 0, 0, 0);
        pfb(gate, 1, 0, 1);
        cp_commit();
        for (int kc = 0; kc < KCH; ++kc) {
            cp_wait0();
            __syncthreads();
            if (kc + 1 < KCH) {
                int nb = ((kc + 1) & 1) * 2;
                pfb(gate, 0, kc + 1, nb);
                pfb(gate, 1, kc + 1, nb + 1);
                cp_commit();
            }
            unsigned PhiA = (kc < 16) ? xhiA : hhiA;
            unsigned PloA = (kc < 16) ? xloA : hloA;
            int uBase = ((kc & 15) * 2);
            unsigned ahi[2][4], alo[2][4], bhi[4][2], blo[4][2];
            load_a(ahi, alo, PhiA, PloA, uBase);
            unsigned slotA = wbA + (unsigned)((kc & 1) * 2) * 8192;
            load_b(bhi, slotA);
            load_b(blo, slotA + 8192);
            #pragma unroll
            for (int mt = 0; mt < 2; ++mt)
                #pragma unroll
                for (int nt = 0; nt < 4; ++nt)
                    mma3(c[mt][nt], ahi[mt], alo[mt], bhi[nt], blo[nt]);
        }
        __syncthreads();
    };

    float cc[2][4][4];

    // ============ phase r: rh = sigmoid(Gr+br)*h -> overwrite h planes ============
    run_phase(1, cc);
    #pragma unroll
    for (int nt = 0; nt < 4; ++nt) {
        int colg = n0w + nt * 8 + 2 * tq;
        int kp   = colg >> 1;
        float b0 = __ldg(br + colg), b1 = __ldg(br + colg + 1);
        #pragma unroll
        for (int mt = 0; mt < 2; ++mt) {
            int r0 = mt * 16 + tg, r1 = r0 + 8;
            int pos = kp ^ (tg << 2);
            float2 hv0 = brecon(hhi[r0 * PL + pos], hlo[r0 * PL + pos]);
            float2 hv1 = brecon(hhi[r1 * PL + pos], hlo[r1 * PL + pos]);
            float v00 = sigf(cc[mt][nt][0] + b0) * hv0.x;
            float v01 = sigf(cc[mt][nt][1] + b1) * hv0.y;
            float v10 = sigf(cc[mt][nt][2] + b0) * hv1.x;
            float v11 = sigf(cc[mt][nt][3] + b1) * hv1.y;
            unsigned hi, lo;
            bsplit(v00, v01, hi, lo); hhi[r0 * PL + pos] = hi; hlo[r0 * PL + pos] = lo;
            bsplit(v10, v11, hi, lo); hhi[r1 * PL + pos] = hi; hlo[r1 * PL + pos] = lo;
        }
    }
    __syncthreads();

    // ============ phase h: hh = tanh(Gh+bh) kept in regs; restage h ============
    run_phase(2, cc);
    float hhreg[2][4][4];
    #pragma unroll
    for (int nt = 0; nt < 4; ++nt) {
        int colg = n0w + nt * 8 + 2 * tq;
        float b0 = __ldg(bh + colg), b1 = __ldg(bh + colg + 1);
        #pragma unroll
        for (int mt = 0; mt < 2; ++mt) {
            hhreg[mt][nt][0] = tanhf(cc[mt][nt][0] + b0);
            hhreg[mt][nt][1] = tanhf(cc[mt][nt][1] + b1);
            hhreg[mt][nt][2] = tanhf(cc[mt][nt][2] + b0);
            hhreg[mt][nt][3] = tanhf(cc[mt][nt][3] + b1);
        }
    }
    // restage h into planes (phase z needs [x|h] again)
    #pragma unroll
    for (int i = tid; i < MT * 64; i += 256) {
        int r  = i >> 6;
        int c4 = (i & 63) << 2;
        int gr = row0 + r;
        float4 vh = make_float4(0.f, 0.f, 0.f, 0.f);
        if (gr < rows) vh = *(const float4*)(h + (size_t)gr * HID + c4);
        int sw = (r & 7) << 2;
        int p0 = (c4 >> 1) ^ sw;
        int p1 = ((c4 >> 1) + 1) ^ sw;
        unsigned hi, lo;
        bsplit(vh.x, vh.y, hi, lo); hhi[r * PL + p0] = hi; hlo[r * PL + p0] = lo;
        bsplit(vh.z, vh.w, hi, lo); hhi[r * PL + p1] = hi; hlo[r * PL + p1] = lo;
    }
    __syncthreads();

    // ============ phase z + final blend ============
    run_phase(0, cc);
    #pragma unroll
    for (int nt = 0; nt < 4; ++nt) {
        int colg = n0w + nt * 8 + 2 * tq;
        int kp   = colg >> 1;
        float b0 = __ldg(bz + colg), b1 = __ldg(bz + colg + 1);
        #pragma unroll
        for (int mt = 0; mt < 2; ++mt) {
            int r0 = mt * 16 + tg, r1 = r0 + 8;
            int pos = kp ^ (tg << 2);
            float2 hv0 = brecon(hhi[r0 * PL + pos], hlo[r0 * PL + pos]);
            float2 hv1 = brecon(hhi[r1 * PL + pos], hlo[r1 * PL + pos]);
            {
                float z0 = sigf(cc[mt][nt][0] + b0);
                float z1 = sigf(cc[mt][nt][1] + b1);
                float o0 = z0 * hv0.x + (1.f - z0) * hhreg[mt][nt][0];
                float o1 = z1 * hv0.y + (1.f - z1) * hhreg[mt][nt][1];
                int gr = row0 + r0;
                if (gr < rows) {
                    *(float2*)(out + (size_t)gr * HID + colg) = make_float2(o0, o1);
                    if (out2) *(float2*)(out2 + (size_t)gr * HID + colg) = make_float2(o0, o1);
                }
            }
            {
                float z0 = sigf(cc[mt][nt][2] + b0);
                float z1 = sigf(cc[mt][nt][3] + b1);
                float o0 = z0 * hv1.x + (1.f - z0) * hhreg[mt][nt][2];
                float o1 = z1 * hv1.y + (1.f - z1) * hhreg[mt][nt][3];
                int gr = row0 + r1;
                if (gr < rows) {
                    *(float2*)(out + (size_t)gr * HID + colg) = make_float2(o0, o1);
                    if (out2) *(float2*)(out2 + (size_t)gr * HID + colg) = make_float2(o0, o1);
                }
            }
        }
    }
}

extern "C" void kernel_launch(void* const* d_in, const int* in_sizes, int n_in,
                              void* d_out, int out_size) {
    const float* x  = (const float*)d_in[0];
    const float* h  = (const float*)d_in[1];
    const float* Wz = (const float*)d_in[2];
    const float* Uz = (const float*)d_in[3];
    const float* bz = (const float*)d_in[4];
    const float* Wr = (const float*)d_in[5];
    const float* Ur = (const float*)d_in[6];
    const float* br = (const float*)d_in[7];
    const float* Wh = (const float*)d_in[8];
    const float* Uh = (const float*)d_in[9];
    const float* bh = (const float*)d_in[10];
    (void)n_in;

    int rows = in_sizes[0] / HID;
    float* out  = (float*)d_out;
    float* out2 = ((long long)out_size >= 2LL * rows * HID) ? out + (size_t)rows * HID : nullptr;

    gru_split_w<<<96, 256>>>(Wz, Uz, Wr, Ur, Wh, Uh);

    const int smem_bytes = (4 * MT * PL + 4 * BLOBU) * (int)sizeof(unsigned); // 98304
    cudaFuncSetAttribute(gru_fused3, cudaFuncAttributeMaxDynamicSharedMemorySize, smem_bytes);

    int grid = (rows + MT - 1) / MT;
    gru_fused3<<<grid, 256, smem_bytes>>>(x, h, bz, br, bh, out, out2, rows);
}

// round 11
// speedup vs baseline: 3.1927x; 1.0315x over previous
#include <cuda_runtime.h>
#include <cstdint>

// Fused GRU cell — bf16 hi/lo split (3 MMAs), mma.sync + ldmatrix, 2 CTA/SM,
// warp-private weight pipeline (no per-chunk CTA barriers).
//   phase r: Gr=[x|h]@[Wr;Ur]; rh=sigmoid(Gr+br)*h overwrites h planes
//   phase h: Gh=[x|rh]@[Wh;Uh]; hh=tanh(Gh+bh) kept in regs; h restaged
//   phase z: Gz=[x|h]@[Wz;Uz]; out = z*h + (1-z)*hh
#define HID   256
#define MT    32
#define PL    128        // uints per A-plane row (512B rows)
#define KCH   32         // k16 chunks over stacked K=512
#define BLOBU 2048       // uints per B chunk blob (8KB)
#define NSLOT 3          // per-warp pipeline depth-2 needs 3 slots
#define SLOTU 4096       // uints per slot (8 warps x 2KB)

// ldmatrix-native B scratch: [gate z/r/h][plane hi/lo][kc][npair16][mat4][row8][4xuint]
__device__ unsigned wsc[3][2][KCH][BLOBU];

__device__ __forceinline__ unsigned sm32(const void* p) {
    return (unsigned)__cvta_generic_to_shared(p);
}
__device__ __forceinline__ void cp16(unsigned s, const void* g) {
    asm volatile("cp.async.cg.shared.global [%0], [%1], 16;\n" :: "r"(s), "l"(g));
}
__device__ __forceinline__ void cp_commit() { asm volatile("cp.async.commit_group;\n"); }
__device__ __forceinline__ void cp_waitg1() { asm volatile("cp.async.wait_group 1;\n" ::: "memory"); }

#define LDSM4(R0,R1,R2,R3,A) \
    asm volatile("ldmatrix.sync.aligned.m8n8.x4.shared.b16 {%0,%1,%2,%3}, [%4];" \
        : "=r"(R0), "=r"(R1), "=r"(R2), "=r"(R3) : "r"(A))

__device__ __forceinline__ void bsplit(float x0, float x1, unsigned& hi, unsigned& lo) {
    asm("cvt.rn.bf16x2.f32 %0, %1, %2;" : "=r"(hi) : "f"(x1), "f"(x0));
    float h0 = __uint_as_float(hi << 16);
    float h1 = __uint_as_float(hi & 0xffff0000u);
    asm("cvt.rn.bf16x2.f32 %0, %1, %2;" : "=r"(lo) : "f"(x1 - h1), "f"(x0 - h0));
}
__device__ __forceinline__ float2 brecon(unsigned hi, unsigned lo) {
    float2 v;
    v.x = __uint_as_float(hi << 16) + __uint_as_float(lo << 16);
    v.y = __uint_as_float(hi & 0xffff0000u) + __uint_as_float(lo & 0xffff0000u);
    return v;
}
__device__ __forceinline__ void mma16(float c[4], const unsigned a[4], const unsigned b[2]) {
    asm volatile(
        "mma.sync.aligned.m16n8k16.row.col.f32.bf16.bf16.f32 "
        "{%0,%1,%2,%3}, {%4,%5,%6,%7}, {%8,%9}, {%0,%1,%2,%3};\n"
        : "+f"(c[0]), "+f"(c[1]), "+f"(c[2]), "+f"(c[3])
        : "r"(a[0]), "r"(a[1]), "r"(a[2]), "r"(a[3]), "r"(b[0]), "r"(b[1]));
}
__device__ __forceinline__ void mma3(float c[4],
                                     const unsigned ahi[4], const unsigned alo[4],
                                     const unsigned bhi[2], const unsigned blo[2]) {
    mma16(c, alo, bhi);
    mma16(c, ahi, blo);
    mma16(c, ahi, bhi);
}
__device__ __forceinline__ float sigf(float v) { return 1.0f / (1.0f + __expf(-v)); }

// ---------------- prologue: split weights into ldmatrix-tiled bf16 hi/lo scratch ------
__global__ void __launch_bounds__(256)
gru_split_w(const float* __restrict__ Wz, const float* __restrict__ Uz,
            const float* __restrict__ Wr, const float* __restrict__ Ur,
            const float* __restrict__ Wh, const float* __restrict__ Uh)
{
    int g  = blockIdx.x >> 5;        // gate 0=z,1=r,2=h
    int kc = blockIdx.x & 31;        // k16 chunk in stacked K
    int n  = threadIdx.x;            // 0..255
    const float* W = (g == 0) ? Wz : (g == 1) ? Wr : Wh;
    const float* U = (g == 0) ? Uz : (g == 1) ? Ur : Uh;
    float v[16];
    #pragma unroll
    for (int k = 0; k < 16; ++k) {
        int kg = kc * 16 + k;
        const float* src = (kg < HID) ? (W + (size_t)kg * HID) : (U + (size_t)(kg - HID) * HID);
        v[k] = src[n];
    }
    int npair = n >> 4, j = n & 7, msel = (n >> 3) & 1;
    unsigned base = npair * 128 + msel * 64 + j * 4;
    #pragma unroll
    for (int usel = 0; usel < 2; ++usel) {
        unsigned h4[4], l4[4];
        #pragma unroll
        for (int q = 0; q < 4; ++q) {
            int kp = usel * 4 + q;
            bsplit(v[2 * kp], v[2 * kp + 1], h4[q], l4[q]);
        }
        unsigned off = base + usel * 32;
        *(uint4*)&wsc[g][0][kc][off] = make_uint4(h4[0], h4[1], h4[2], h4[3]);
        *(uint4*)&wsc[g][1][kc][off] = make_uint4(l4[0], l4[1], l4[2], l4[3]);
    }
}

// ---------------- main fused kernel ----------------
__global__ void __launch_bounds__(256, 2)
gru_fused3(const float* __restrict__ x,  const float* __restrict__ h,
           const float* __restrict__ bz, const float* __restrict__ br,
           const float* __restrict__ bh,
           float* __restrict__ out, float* __restrict__ out2, int rows)
{
    extern __shared__ unsigned smem_u[];
    unsigned* xhi = smem_u;              // 32 x 128 uints each (16KB)
    unsigned* xlo = xhi + MT * PL;
    unsigned* hhi = xlo + MT * PL;       // holds h, then rh, then h again
    unsigned* hlo = hhi + MT * PL;
    unsigned* wb  = hlo + MT * PL;       // NSLOT slots x 4096 uints

    const int tid  = threadIdx.x;
    const int lane = tid & 31;
    const int warp = tid >> 5;
    const int tg   = lane >> 2;
    const int tq   = lane & 3;
    const int n0w  = warp * 32;
    const int row0 = blockIdx.x * MT;

    const unsigned xhiA = sm32(xhi), xloA = sm32(xlo);
    const unsigned hhiA = sm32(hhi), hloA = sm32(hlo);
    const unsigned wbA  = sm32(wb);
    const unsigned wslice = wbA + (unsigned)warp * 2048;   // this warp's region in slot 0

    // ---- stage x/h into split packed swizzled planes ----
    #pragma unroll
    for (int i = tid; i < MT * 64; i += 256) {
        int r  = i >> 6;
        int c4 = (i & 63) << 2;
        int gr = row0 + r;
        float4 vx = make_float4(0.f, 0.f, 0.f, 0.f), vh = vx;
        if (gr < rows) {
            vx = *(const float4*)(x + (size_t)gr * HID + c4);
            vh = *(const float4*)(h + (size_t)gr * HID + c4);
        }
        int sw = (r & 7) << 2;
        int p0 = (c4 >> 1) ^ sw;
        int p1 = ((c4 >> 1) + 1) ^ sw;
        unsigned hi, lo;
        bsplit(vx.x, vx.y, hi, lo); xhi[r * PL + p0] = hi; xlo[r * PL + p0] = lo;
        bsplit(vx.z, vx.w, hi, lo); xhi[r * PL + p1] = hi; xlo[r * PL + p1] = lo;
        bsplit(vh.x, vh.y, hi, lo); hhi[r * PL + p0] = hi; hlo[r * PL + p0] = lo;
        bsplit(vh.z, vh.w, hi, lo); hhi[r * PL + p1] = hi; hlo[r * PL + p1] = lo;
    }
    __syncthreads();

    // warp-private copy of this warp's 2KB slice (hi 1KB + lo 1KB) of chunk kc
    auto pfw = [&](int gate, int kc, int slot) {
        const unsigned* srcHi = &wsc[gate][0][kc][warp * 256];
        const unsigned* srcLo = &wsc[gate][1][kc][warp * 256];
        unsigned dst = wslice + (unsigned)slot * 16384;
        cp16(dst + lane * 16,        srcHi + lane * 4);
        cp16(dst + 512 + lane * 16,  srcHi + 128 + lane * 4);
        cp16(dst + 1024 + lane * 16, srcLo + lane * 4);
        cp16(dst + 1536 + lane * 16, srcLo + 128 + lane * 4);
    };

    // ldmatrix lane geometry
    const int aRowOff = (lane & 7) + ((lane >> 3) & 1) * 8;
    const int aUsel   = (lane >> 4) & 1;
    const unsigned bOff = (unsigned)((lane >> 3) * 128 + (lane & 7) * 16);

    auto load_a = [&](unsigned ahi[2][4], unsigned alo[2][4],
                      unsigned PhiA, unsigned PloA, int uBase) {
        #pragma unroll
        for (int mt = 0; mt < 2; ++mt) {
            int rowA = mt * 16 + aRowOff;
            unsigned swu = (unsigned)(((uBase + aUsel) ^ (rowA & 7)) << 4);
            unsigned byteOff = (unsigned)rowA * 512u + swu;
            LDSM4(ahi[mt][0], ahi[mt][1], ahi[mt][2], ahi[mt][3], PhiA + byteOff);
            LDSM4(alo[mt][0], alo[mt][1], alo[mt][2], alo[mt][3], PloA + byteOff);
        }
    };
    auto load_b = [&](unsigned bf[4][2], unsigned base) {
        LDSM4(bf[0][0], bf[0][1], bf[1][0], bf[1][1], base + bOff);
        LDSM4(bf[2][0], bf[2][1], bf[3][0], bf[3][1], base + 512 + bOff);
    };

    // one gate GEMM over stacked K=512, full N=256 — warp-decoupled pipeline
    auto run_phase = [&](int gate, float (*c)[4][4]) {
        #pragma unroll
        for (int i = 0; i < 2; ++i)
            #pragma unroll
            for (int j = 0; j < 4; ++j)
                #pragma unroll
                for (int q = 0; q < 4; ++q) c[i][j][q] = 0.f;
        pfw(gate, 0, 0); cp_commit();
        pfw(gate, 1, 1); cp_commit();
        int slot = 0;
        for (int kc = 0; kc < KCH; ++kc) {
            cp_waitg1();
            __syncwarp();
            if (kc + 2 < KCH) pfw(gate, kc + 2, (slot + 2) % NSLOT);
            cp_commit();                           // empty group at tail keeps count sound
            unsigned PhiA = (kc < 16) ? xhiA : hhiA;
            unsigned PloA = (kc < 16) ? xloA : hloA;
            int uBase = ((kc & 15) * 2);
            unsigned ahi[2][4], alo[2][4], bhi[4][2], blo[4][2];
            load_a(ahi, alo, PhiA, PloA, uBase);
            unsigned base = wslice + (unsigned)slot * 16384;
            load_b(bhi, base);
            load_b(blo, base + 1024);
            #pragma unroll
            for (int mt = 0; mt < 2; ++mt)
                #pragma unroll
                for (int nt = 0; nt < 4; ++nt)
                    mma3(c[mt][nt], ahi[mt], alo[mt], bhi[nt], blo[nt]);
            slot = (slot + 1) % NSLOT;
        }
        __syncthreads();
    };

    float cc[2][4][4];

    // ============ phase r: rh = sigmoid(Gr+br)*h -> overwrite h planes ============
    run_phase(1, cc);
    #pragma unroll
    for (int nt = 0; nt < 4; ++nt) {
        int colg = n0w + nt * 8 + 2 * tq;
        int kp   = colg >> 1;
        float b0 = __ldg(br + colg), b1 = __ldg(br + colg + 1);
        #pragma unroll
        for (int mt = 0; mt < 2; ++mt) {
            int r0 = mt * 16 + tg, r1 = r0 + 8;
            int pos = kp ^ (tg << 2);
            float2 hv0 = brecon(hhi[r0 * PL + pos], hlo[r0 * PL + pos]);
            float2 hv1 = brecon(hhi[r1 * PL + pos], hlo[r1 * PL + pos]);
            float v00 = sigf(cc[mt][nt][0] + b0) * hv0.x;
            float v01 = sigf(cc[mt][nt][1] + b1) * hv0.y;
            float v10 = sigf(cc[mt][nt][2] + b0) * hv1.x;
            float v11 = sigf(cc[mt][nt][3] + b1) * hv1.y;
            unsigned hi, lo;
            bsplit(v00, v01, hi, lo); hhi[r0 * PL + pos] = hi; hlo[r0 * PL + pos] = lo;
            bsplit(v10, v11, hi, lo); hhi[r1 * PL + pos] = hi; hlo[r1 * PL + pos] = lo;
        }
    }
    __syncthreads();

    // ============ phase h: hh = tanh(Gh+bh) kept in regs; restage h ============
    run_phase(2, cc);
    float hhreg[2][4][4];
    #pragma unroll
    for (int nt = 0; nt < 4; ++nt) {
        int colg = n0w + nt * 8 + 2 * tq;
        float b0 = __ldg(bh + colg), b1 = __ldg(bh + colg + 1);
        #pragma unroll
        for (int mt = 0; mt < 2; ++mt) {
            hhreg[mt][nt][0] = tanhf(cc[mt][nt][0] + b0);
            hhreg[mt][nt][1] = tanhf(cc[mt][nt][1] + b1);
            hhreg[mt][nt][2] = tanhf(cc[mt][nt][2] + b0);
            hhreg[mt][nt][3] = tanhf(cc[mt][nt][3] + b1);
        }
    }
    // restage h into planes (phase z needs [x|h] again)
    #pragma unroll
    for (int i = tid; i < MT * 64; i += 256) {
        int r  = i >> 6;
        int c4 = (i & 63) << 2;
        int gr = row0 + r;
        float4 vh = make_float4(0.f, 0.f, 0.f, 0.f);
        if (gr < rows) vh = *(const float4*)(h + (size_t)gr * HID + c4);
        int sw = (r & 7) << 2;
        int p0 = (c4 >> 1) ^ sw;
        int p1 = ((c4 >> 1) + 1) ^ sw;
        unsigned hi, lo;
        bsplit(vh.x, vh.y, hi, lo); hhi[r * PL + p0] = hi; hlo[r * PL + p0] = lo;
        bsplit(vh.z, vh.w, hi, lo); hhi[r * PL + p1] = hi; hlo[r * PL + p1] = lo;
    }
    __syncthreads();

    // ============ phase z + final blend ============
    run_phase(0, cc);
    #pragma unroll
    for (int nt = 0; nt < 4; ++nt) {
        int colg = n0w + nt * 8 + 2 * tq;
        int kp   = colg >> 1;
        float b0 = __ldg(bz + colg), b1 = __ldg(bz + colg + 1);
        #pragma unroll
        for (int mt = 0; mt < 2; ++mt) {
            int r0 = mt * 16 + tg, r1 = r0 + 8;
            int pos = kp ^ (tg << 2);
            float2 hv0 = brecon(hhi[r0 * PL + pos], hlo[r0 * PL + pos]);
            float2 hv1 = brecon(hhi[r1 * PL + pos], hlo[r1 * PL + pos]);
            {
                float z0 = sigf(cc[mt][nt][0] + b0);
                float z1 = sigf(cc[mt][nt][1] + b1);
                float o0 = z0 * hv0.x + (1.f - z0) * hhreg[mt][nt][0];
                float o1 = z1 * hv0.y + (1.f - z1) * hhreg[mt][nt][1];
                int gr = row0 + r0;
                if (gr < rows) {
                    *(float2*)(out + (size_t)gr * HID + colg) = make_float2(o0, o1);
                    if (out2) *(float2*)(out2 + (size_t)gr * HID + colg) = make_float2(o0, o1);
                }
            }
            {
                float z0 = sigf(cc[mt][nt][2] + b0);
                float z1 = sigf(cc[mt][nt][3] + b1);
                float o0 = z0 * hv1.x + (1.f - z0) * hhreg[mt][nt][2];
                float o1 = z1 * hv1.y + (1.f - z1) * hhreg[mt][nt][3];
                int gr = row0 + r1;
                if (gr < rows) {
                    *(float2*)(out + (size_t)gr * HID + colg) = make_float2(o0, o1);
                    if (out2) *(float2*)(out2 + (size_t)gr * HID + colg) = make_float2(o0, o1);
                }
            }
        }
    }
}

extern "C" void kernel_launch(void* const* d_in, const int* in_sizes, int n_in,
                              void* d_out, int out_size) {
    const float* x  = (const float*)d_in[0];
    const float* h  = (const float*)d_in[1];
    const float* Wz = (const float*)d_in[2];
    const float* Uz = (const float*)d_in[3];
    const float* bz = (const float*)d_in[4];
    const float* Wr = (const float*)d_in[5];
    const float* Ur = (const float*)d_in[6];
    const float* br = (const float*)d_in[7];
    const float* Wh = (const float*)d_in[8];
    const float* Uh = (const float*)d_in[9];
    const float* bh = (const float*)d_in[10];
    (void)n_in;

    int rows = in_sizes[0] / HID;
    float* out  = (float*)d_out;
    float* out2 = ((long long)out_size >= 2LL * rows * HID) ? out + (size_t)rows * HID : nullptr;

    gru_split_w<<<96, 256>>>(Wz, Uz, Wr, Ur, Wh, Uh);

    const int smem_bytes = (4 * MT * PL + NSLOT * SLOTU) * (int)sizeof(unsigned); // 114688
    cudaFuncSetAttribute(gru_fused3, cudaFuncAttributeMaxDynamicSharedMemorySize, smem_bytes);

    int grid = (rows + MT - 1) / MT;
    gru_fused3<<<grid, 256, smem_bytes>>>(x, h, bz, br, bh, out, out2, rows);
}

// round 12
// speedup vs baseline: 3.4673x; 1.0860x over previous
#include <cuda_runtime.h>
#include <cstdint>

// Fused GRU cell — bf16 hi/lo split (3 MMAs), mma.sync + ldmatrix, 2 CTA/SM,
// warp-private weight pipeline, r+z gates fused into one GEMM pass.
//   pass 1: Gr,Gz = [x|h]@([Wr;Ur],[Wz;Uz]); z kept in regs; rh overwrites h planes
//   pass 2: Gh = [x|rh]@[Wh;Uh]; out = z*h + (1-z)*tanh(Gh+bh)  (h re-read from gmem)
#define HID   256
#define MT    32
#define PL    128        // uints per A-plane row (512B rows)
#define KCH   32         // k16 chunks over stacked K=512
#define BLOBU 2048       // uints per B chunk blob (8KB)
#define NSLOT 3
#define SLOTU 4096       // uints per slot (8 warps x 2KB)

// ldmatrix-native B scratch: [gate z/r/h][plane hi/lo][kc][npair16][mat4][row8][4xuint]
__device__ unsigned wsc[3][2][KCH][BLOBU];

__device__ __forceinline__ unsigned sm32(const void* p) {
    return (unsigned)__cvta_generic_to_shared(p);
}
__device__ __forceinline__ void cp16(unsigned s, const void* g) {
    asm volatile("cp.async.cg.shared.global [%0], [%1], 16;\n" :: "r"(s), "l"(g));
}
__device__ __forceinline__ void cp_commit() { asm volatile("cp.async.commit_group;\n"); }
__device__ __forceinline__ void cp_waitg1() { asm volatile("cp.async.wait_group 1;\n" ::: "memory"); }

#define LDSM4(R0,R1,R2,R3,A) \
    asm volatile("ldmatrix.sync.aligned.m8n8.x4.shared.b16 {%0,%1,%2,%3}, [%4];" \
        : "=r"(R0), "=r"(R1), "=r"(R2), "=r"(R3) : "r"(A))

__device__ __forceinline__ void bsplit(float x0, float x1, unsigned& hi, unsigned& lo) {
    asm("cvt.rn.bf16x2.f32 %0, %1, %2;" : "=r"(hi) : "f"(x1), "f"(x0));
    float h0 = __uint_as_float(hi << 16);
    float h1 = __uint_as_float(hi & 0xffff0000u);
    asm("cvt.rn.bf16x2.f32 %0, %1, %2;" : "=r"(lo) : "f"(x1 - h1), "f"(x0 - h0));
}
__device__ __forceinline__ float2 brecon(unsigned hi, unsigned lo) {
    float2 v;
    v.x = __uint_as_float(hi << 16) + __uint_as_float(lo << 16);
    v.y = __uint_as_float(hi & 0xffff0000u) + __uint_as_float(lo & 0xffff0000u);
    return v;
}
__device__ __forceinline__ void mma16(float c[4], const unsigned a[4], const unsigned b[2]) {
    asm volatile(
        "mma.sync.aligned.m16n8k16.row.col.f32.bf16.bf16.f32 "
        "{%0,%1,%2,%3}, {%4,%5,%6,%7}, {%8,%9}, {%0,%1,%2,%3};\n"
        : "+f"(c[0]), "+f"(c[1]), "+f"(c[2]), "+f"(c[3])
        : "r"(a[0]), "r"(a[1]), "r"(a[2]), "r"(a[3]), "r"(b[0]), "r"(b[1]));
}
__device__ __forceinline__ void mma3(float c[4],
                                     const unsigned ahi[4], const unsigned alo[4],
                                     const unsigned bhi[2], const unsigned blo[2]) {
    mma16(c, alo, bhi);
    mma16(c, ahi, blo);
    mma16(c, ahi, bhi);
}
__device__ __forceinline__ float sigf(float v) { return 1.0f / (1.0f + __expf(-v)); }

// ---------------- prologue: split weights into ldmatrix-tiled bf16 hi/lo scratch ------
__global__ void __launch_bounds__(256)
gru_split_w(const float* __restrict__ Wz, const float* __restrict__ Uz,
            const float* __restrict__ Wr, const float* __restrict__ Ur,
            const float* __restrict__ Wh, const float* __restrict__ Uh)
{
    int g  = blockIdx.x >> 5;        // gate 0=z,1=r,2=h
    int kc = blockIdx.x & 31;        // k16 chunk in stacked K
    int n  = threadIdx.x;            // 0..255
    const float* W = (g == 0) ? Wz : (g == 1) ? Wr : Wh;
    const float* U = (g == 0) ? Uz : (g == 1) ? Ur : Uh;
    float v[16];
    #pragma unroll
    for (int k = 0; k < 16; ++k) {
        int kg = kc * 16 + k;
        const float* src = (kg < HID) ? (W + (size_t)kg * HID) : (U + (size_t)(kg - HID) * HID);
        v[k] = src[n];
    }
    int npair = n >> 4, j = n & 7, msel = (n >> 3) & 1;
    unsigned base = npair * 128 + msel * 64 + j * 4;
    #pragma unroll
    for (int usel = 0; usel < 2; ++usel) {
        unsigned h4[4], l4[4];
        #pragma unroll
        for (int q = 0; q < 4; ++q) {
            int kp = usel * 4 + q;
            bsplit(v[2 * kp], v[2 * kp + 1], h4[q], l4[q]);
        }
        unsigned off = base + usel * 32;
        *(uint4*)&wsc[g][0][kc][off] = make_uint4(h4[0], h4[1], h4[2], h4[3]);
        *(uint4*)&wsc[g][1][kc][off] = make_uint4(l4[0], l4[1], l4[2], l4[3]);
    }
}

// ---------------- main fused kernel ----------------
__global__ void __launch_bounds__(256, 2)
gru_fused3(const float* __restrict__ x,  const float* __restrict__ h,
           const float* __restrict__ bz, const float* __restrict__ br,
           const float* __restrict__ bh,
           float* __restrict__ out, float* __restrict__ out2, int rows)
{
    extern __shared__ unsigned smem_u[];
    unsigned* xhi = smem_u;              // 32 x 128 uints each (16KB)
    unsigned* xlo = xhi + MT * PL;
    unsigned* hhi = xlo + MT * PL;       // holds h, then rh
    unsigned* hlo = hhi + MT * PL;
    unsigned* wb  = hlo + MT * PL;       // NSLOT slots x 4096 uints

    const int tid  = threadIdx.x;
    const int lane = tid & 31;
    const int warp = tid >> 5;
    const int tg   = lane >> 2;
    const int tq   = lane & 3;
    const int n0w  = warp * 32;
    const int row0 = blockIdx.x * MT;

    const unsigned xhiA = sm32(xhi), xloA = sm32(xlo);
    const unsigned hhiA = sm32(hhi), hloA = sm32(hlo);
    const unsigned wbA  = sm32(wb);
    const unsigned wslice = wbA + (unsigned)warp * 2048;

    // ---- stage x/h into split packed swizzled planes ----
    #pragma unroll
    for (int i = tid; i < MT * 64; i += 256) {
        int r  = i >> 6;
        int c4 = (i & 63) << 2;
        int gr = row0 + r;
        float4 vx = make_float4(0.f, 0.f, 0.f, 0.f), vh = vx;
        if (gr < rows) {
            vx = *(const float4*)(x + (size_t)gr * HID + c4);
            vh = *(const float4*)(h + (size_t)gr * HID + c4);
        }
        int sw = (r & 7) << 2;
        int p0 = (c4 >> 1) ^ sw;
        int p1 = ((c4 >> 1) + 1) ^ sw;
        unsigned hi, lo;
        bsplit(vx.x, vx.y, hi, lo); xhi[r * PL + p0] = hi; xlo[r * PL + p0] = lo;
        bsplit(vx.z, vx.w, hi, lo); xhi[r * PL + p1] = hi; xlo[r * PL + p1] = lo;
        bsplit(vh.x, vh.y, hi, lo); hhi[r * PL + p0] = hi; hlo[r * PL + p0] = lo;
        bsplit(vh.z, vh.w, hi, lo); hhi[r * PL + p1] = hi; hlo[r * PL + p1] = lo;
    }
    __syncthreads();

    // warp-private copy of this warp's 2KB slice (hi 1KB + lo 1KB) of chunk kc
    auto pfw = [&](int gate, int kc, int slot) {
        const unsigned* srcHi = &wsc[gate][0][kc][warp * 256];
        const unsigned* srcLo = &wsc[gate][1][kc][warp * 256];
        unsigned dst = wslice + (unsigned)slot * 16384;
        cp16(dst + lane * 16,        srcHi + lane * 4);
        cp16(dst + 512 + lane * 16,  srcHi + 128 + lane * 4);
        cp16(dst + 1024 + lane * 16, srcLo + lane * 4);
        cp16(dst + 1536 + lane * 16, srcLo + 128 + lane * 4);
    };

    // ldmatrix lane geometry
    const int aRowOff = (lane & 7) + ((lane >> 3) & 1) * 8;
    const int aUsel   = (lane >> 4) & 1;
    const unsigned bOff = (unsigned)((lane >> 3) * 128 + (lane & 7) * 16);

    auto load_a = [&](unsigned ahi[2][4], unsigned alo[2][4],
                      unsigned PhiA, unsigned PloA, int uBase) {
        #pragma unroll
        for (int mt = 0; mt < 2; ++mt) {
            int rowA = mt * 16 + aRowOff;
            unsigned swu = (unsigned)(((uBase + aUsel) ^ (rowA & 7)) << 4);
            unsigned byteOff = (unsigned)rowA * 512u + swu;
            LDSM4(ahi[mt][0], ahi[mt][1], ahi[mt][2], ahi[mt][3], PhiA + byteOff);
            LDSM4(alo[mt][0], alo[mt][1], alo[mt][2], alo[mt][3], PloA + byteOff);
        }
    };
    auto load_b = [&](unsigned bf[4][2], unsigned base) {
        LDSM4(bf[0][0], bf[0][1], bf[1][0], bf[1][1], base + bOff);
        LDSM4(bf[2][0], bf[2][1], bf[3][0], bf[3][1], base + 512 + bOff);
    };

    float cr[2][4][4], cz[2][4][4];
    #pragma unroll
    for (int i = 0; i < 2; ++i)
        #pragma unroll
        for (int j = 0; j < 4; ++j)
            #pragma unroll
            for (int q = 0; q < 4; ++q) { cr[i][j][q] = 0.f; cz[i][j][q] = 0.f; }

    // ============ pass 1: Gr + Gz over [x|h], interleaved entries ============
    {
        pfw(1, 0, 0); cp_commit();      // entry 0: gate r chunk 0
        pfw(0, 0, 1); cp_commit();      // entry 1: gate z chunk 0
        int slot = 0;
        unsigned ahi[2][4], alo[2][4];
        for (int e = 0; e < 2 * KCH; ++e) {
            cp_waitg1();
            __syncwarp();
            int en = e + 2;
            if (en < 2 * KCH) {
                int s2 = slot + 2; if (s2 >= NSLOT) s2 -= NSLOT;
                pfw((en & 1) ? 0 : 1, en >> 1, s2);
            }
            cp_commit();
            int kc = e >> 1;
            if ((e & 1) == 0) {
                unsigned PhiA = (kc < 16) ? xhiA : hhiA;
                unsigned PloA = (kc < 16) ? xloA : hloA;
                load_a(ahi, alo, PhiA, PloA, (kc & 15) * 2);
            }
            unsigned bhi[4][2], blo[4][2];
            unsigned base = wslice + (unsigned)slot * 16384;
            load_b(bhi, base);
            load_b(blo, base + 1024);
            float (*c)[4] = (e & 1) ? cz[0] : cr[0];
            #pragma unroll
            for (int mt = 0; mt < 2; ++mt)
                #pragma unroll
                for (int nt = 0; nt < 4; ++nt)
                    mma3((e & 1) ? cz[mt][nt] : cr[mt][nt], ahi[mt], alo[mt], bhi[nt], blo[nt]);
            (void)c;
            slot = slot + 1; if (slot >= NSLOT) slot = 0;
        }
        __syncthreads();
    }

    // ============ epilogue 1: z kept in regs; rh = sigmoid(Gr+br)*h overwrites h planes
    float zreg[2][4][4];
    #pragma unroll
    for (int nt = 0; nt < 4; ++nt) {
        int colg = n0w + nt * 8 + 2 * tq;
        int kp   = colg >> 1;
        float br0 = __ldg(br + colg), br1 = __ldg(br + colg + 1);
        float bz0 = __ldg(bz + colg), bz1 = __ldg(bz + colg + 1);
        #pragma unroll
        for (int mt = 0; mt < 2; ++mt) {
            int r0 = mt * 16 + tg, r1 = r0 + 8;
            int pos = kp ^ (tg << 2);
            float2 hv0 = brecon(hhi[r0 * PL + pos], hlo[r0 * PL + pos]);
            float2 hv1 = brecon(hhi[r1 * PL + pos], hlo[r1 * PL + pos]);
            zreg[mt][nt][0] = sigf(cz[mt][nt][0] + bz0);
            zreg[mt][nt][1] = sigf(cz[mt][nt][1] + bz1);
            zreg[mt][nt][2] = sigf(cz[mt][nt][2] + bz0);
            zreg[mt][nt][3] = sigf(cz[mt][nt][3] + bz1);
            float v00 = sigf(cr[mt][nt][0] + br0) * hv0.x;
            float v01 = sigf(cr[mt][nt][1] + br1) * hv0.y;
            float v10 = sigf(cr[mt][nt][2] + br0) * hv1.x;
            float v11 = sigf(cr[mt][nt][3] + br1) * hv1.y;
            unsigned hi, lo;
            bsplit(v00, v01, hi, lo); hhi[r0 * PL + pos] = hi; hlo[r0 * PL + pos] = lo;
            bsplit(v10, v11, hi, lo); hhi[r1 * PL + pos] = hi; hlo[r1 * PL + pos] = lo;
        }
    }
    __syncthreads();

    // ============ pass 2: Gh over [x|rh] ============
    float ch[2][4][4];
    #pragma unroll
    for (int i = 0; i < 2; ++i)
        #pragma unroll
        for (int j = 0; j < 4; ++j)
            #pragma unroll
            for (int q = 0; q < 4; ++q) ch[i][j][q] = 0.f;
    {
        pfw(2, 0, 0); cp_commit();
        pfw(2, 1, 1); cp_commit();
        int slot = 0;
        for (int kc = 0; kc < KCH; ++kc) {
            cp_waitg1();
            __syncwarp();
            if (kc + 2 < KCH) {
                int s2 = slot + 2; if (s2 >= NSLOT) s2 -= NSLOT;
                pfw(2, kc + 2, s2);
            }
            cp_commit();
            unsigned PhiA = (kc < 16) ? xhiA : hhiA;
            unsigned PloA = (kc < 16) ? xloA : hloA;
            unsigned ahi[2][4], alo[2][4], bhi[4][2], blo[4][2];
            load_a(ahi, alo, PhiA, PloA, (kc & 15) * 2);
            unsigned base = wslice + (unsigned)slot * 16384;
            load_b(bhi, base);
            load_b(blo, base + 1024);
            #pragma unroll
            for (int mt = 0; mt < 2; ++mt)
                #pragma unroll
                for (int nt = 0; nt < 4; ++nt)
                    mma3(ch[mt][nt], ahi[mt], alo[mt], bhi[nt], blo[nt]);
            slot = slot + 1; if (slot >= NSLOT) slot = 0;
        }
    }

    // ============ final blend: out = z*h + (1-z)*tanh(Gh+bh), h from gmem ============
    #pragma unroll
    for (int nt = 0; nt < 4; ++nt) {
        int colg = n0w + nt * 8 + 2 * tq;
        float b0 = __ldg(bh + colg), b1 = __ldg(bh + colg + 1);
        #pragma unroll
        for (int mt = 0; mt < 2; ++mt) {
            int r0 = mt * 16 + tg, r1 = r0 + 8;
            int gr0 = row0 + r0, gr1 = row0 + r1;
            if (gr0 < rows) {
                float2 hv = *(const float2*)(h + (size_t)gr0 * HID + colg);
                float z0 = zreg[mt][nt][0], z1 = zreg[mt][nt][1];
                float t0 = tanhf(ch[mt][nt][0] + b0);
                float t1 = tanhf(ch[mt][nt][1] + b1);
                float o0 = z0 * hv.x + (1.f - z0) * t0;
                float o1 = z1 * hv.y + (1.f - z1) * t1;
                *(float2*)(out + (size_t)gr0 * HID + colg) = make_float2(o0, o1);
                if (out2) *(float2*)(out2 + (size_t)gr0 * HID + colg) = make_float2(o0, o1);
            }
            if (gr1 < rows) {
                float2 hv = *(const float2*)(h + (size_t)gr1 * HID + colg);
                float z0 = zreg[mt][nt][2], z1 = zreg[mt][nt][3];
                float t0 = tanhf(ch[mt][nt][2] + b0);
                float t1 = tanhf(ch[mt][nt][3] + b1);
                float o0 = z0 * hv.x + (1.f - z0) * t0;
                float o1 = z1 * hv.y + (1.f - z1) * t1;
                *(float2*)(out + (size_t)gr1 * HID + colg) = make_float2(o0, o1);
                if (out2) *(float2*)(out2 + (size_t)gr1 * HID + colg) = make_float2(o0, o1);
            }
        }
    }
}

extern "C" void kernel_launch(void* const* d_in, const int* in_sizes, int n_in,
                              void* d_out, int out_size) {
    const float* x  = (const float*)d_in[0];
    const float* h  = (const float*)d_in[1];
    const float* Wz = (const float*)d_in[2];
    const float* Uz = (const float*)d_in[3];
    const float* bz = (const float*)d_in[4];
    const float* Wr = (const float*)d_in[5];
    const float* Ur = (const float*)d_in[6];
    const float* br = (const float*)d_in[7];
    const float* Wh = (const float*)d_in[8];
    const float* Uh = (const float*)d_in[9];
    const float* bh = (const float*)d_in[10];
    (void)n_in;

    int rows = in_sizes[0] / HID;
    float* out  = (float*)d_out;
    float* out2 = ((long long)out_size >= 2LL * rows * HID) ? out + (size_t)rows * HID : nullptr;

    gru_split_w<<<96, 256>>>(Wz, Uz, Wr, Ur, Wh, Uh);

    const int smem_bytes = (4 * MT * PL + NSLOT * SLOTU) * (int)sizeof(unsigned); // 114688
    cudaFuncSetAttribute(gru_fused3, cudaFuncAttributeMaxDynamicSharedMemorySize, smem_bytes);

    int grid = (rows + MT - 1) / MT;
    gru_fused3<<<grid, 256, smem_bytes>>>(x, h, bz, br, bh, out, out2, rows);
}